// round 1
// baseline (speedup 1.0000x reference)
#include <cuda_runtime.h>
#include <math.h>

#define B 8
#define L 2048
#define D 1024

// 128 MB scratch for masked scores + per-row softmax stats.
__device__ float g_scores[(size_t)B * L * L];
__device__ float g_rowmax[B * L];
__device__ float g_rowscale[B * L];   // m_i / denom

// ---------------------------------------------------------------------------
// Kernel 1: S[b,i,j] = (q[b,i,:] . k[b,j,:]) * m_i * m_j
// 128x128 C-tile, BK=16, 256 threads, 8x8 per-thread microtile.
// ---------------------------------------------------------------------------
__global__ __launch_bounds__(256) void qk_kernel(
    const float* __restrict__ q, const float* __restrict__ k,
    const int* __restrict__ mask)
{
    __shared__ float As[16][128];
    __shared__ float Bs[16][128];

    const int b  = blockIdx.z;
    const int ti = blockIdx.y * 128;
    const int tj = blockIdx.x * 128;
    const float* __restrict__ qb = q + (size_t)b * L * D;
    const float* __restrict__ kb = k + (size_t)b * L * D;

    const int tid = threadIdx.x;
    const int lr  = tid >> 2;          // 0..63
    const int lc  = (tid & 3) << 2;    // 0,4,8,12
    const int tx  = tid & 15;
    const int ty  = tid >> 4;

    float acc[8][8];
    #pragma unroll
    for (int i = 0; i < 8; i++)
        #pragma unroll
        for (int j = 0; j < 8; j++) acc[i][j] = 0.0f;

    for (int k0 = 0; k0 < D; k0 += 16) {
        #pragma unroll
        for (int h = 0; h < 2; h++) {
            int r = lr + h * 64;
            float4 va = *(const float4*)(qb + (size_t)(ti + r) * D + k0 + lc);
            As[lc + 0][r] = va.x; As[lc + 1][r] = va.y;
            As[lc + 2][r] = va.z; As[lc + 3][r] = va.w;
            float4 vb = *(const float4*)(kb + (size_t)(tj + r) * D + k0 + lc);
            Bs[lc + 0][r] = vb.x; Bs[lc + 1][r] = vb.y;
            Bs[lc + 2][r] = vb.z; Bs[lc + 3][r] = vb.w;
        }
        __syncthreads();
        #pragma unroll
        for (int kk = 0; kk < 16; kk++) {
            float4 a0 = *(const float4*)&As[kk][ty * 4];
            float4 a1 = *(const float4*)&As[kk][64 + ty * 4];
            float4 b0 = *(const float4*)&Bs[kk][tx * 4];
            float4 b1 = *(const float4*)&Bs[kk][64 + tx * 4];
            float a[8]  = {a0.x, a0.y, a0.z, a0.w, a1.x, a1.y, a1.z, a1.w};
            float bb[8] = {b0.x, b0.y, b0.z, b0.w, b1.x, b1.y, b1.z, b1.w};
            #pragma unroll
            for (int i = 0; i < 8; i++)
                #pragma unroll
                for (int j = 0; j < 8; j++)
                    acc[i][j] = fmaf(a[i], bb[j], acc[i][j]);
        }
        __syncthreads();
    }

    const int* mrow = mask + b * L + ti;
    const int* mcol = mask + b * L + tj;
    float mj[8];
    #pragma unroll
    for (int j = 0; j < 4; j++) {
        mj[j]     = (float)mcol[tx * 4 + j];
        mj[4 + j] = (float)mcol[64 + tx * 4 + j];
    }
    float* srow = g_scores + ((size_t)b * L + ti) * L + tj;
    #pragma unroll
    for (int i = 0; i < 8; i++) {
        int r = (i < 4) ? (ty * 4 + i) : (64 + ty * 4 + (i - 4));
        float mi = (float)mrow[r];
        float4 o0 = make_float4(acc[i][0] * mi * mj[0], acc[i][1] * mi * mj[1],
                                acc[i][2] * mi * mj[2], acc[i][3] * mi * mj[3]);
        float4 o1 = make_float4(acc[i][4] * mi * mj[4], acc[i][5] * mi * mj[5],
                                acc[i][6] * mi * mj[6], acc[i][7] * mi * mj[7]);
        *(float4*)(srow + (size_t)r * L + tx * 4)      = o0;
        *(float4*)(srow + (size_t)r * L + 64 + tx * 4) = o1;
    }
}

// ---------------------------------------------------------------------------
// Kernel 2: per-row max (over masked scores, zeros included) and
// scale = m_i / (sum(exp(s - max) * m_j) + (sum==0) + 1e-20)
// One 256-thread block per row (2048 elements).
// ---------------------------------------------------------------------------
__global__ __launch_bounds__(256) void rowstats_kernel(const int* __restrict__ mask)
{
    const int row = blockIdx.x;            // b*L + i
    const int b   = row >> 11;
    const int i   = row & (L - 1);
    const float* s = g_scores + (size_t)row * L;
    const int* mb  = mask + b * L;
    const int tid  = threadIdx.x;
    const int base = tid * 8;

    float v[8], m[8];
    float4 v0 = *(const float4*)(s + base);
    float4 v1 = *(const float4*)(s + base + 4);
    int4  m0 = *(const int4*)(mb + base);
    int4  m1 = *(const int4*)(mb + base + 4);
    v[0] = v0.x; v[1] = v0.y; v[2] = v0.z; v[3] = v0.w;
    v[4] = v1.x; v[5] = v1.y; v[6] = v1.z; v[7] = v1.w;
    m[0] = (float)m0.x; m[1] = (float)m0.y; m[2] = (float)m0.z; m[3] = (float)m0.w;
    m[4] = (float)m1.x; m[5] = (float)m1.y; m[6] = (float)m1.z; m[7] = (float)m1.w;

    float lmax = v[0];
    #pragma unroll
    for (int e = 1; e < 8; e++) lmax = fmaxf(lmax, v[e]);

    __shared__ float sred[8];
    const unsigned full = 0xffffffffu;
    #pragma unroll
    for (int o = 16; o > 0; o >>= 1) lmax = fmaxf(lmax, __shfl_xor_sync(full, lmax, o));
    if ((tid & 31) == 0) sred[tid >> 5] = lmax;
    __syncthreads();
    if (tid < 32) {
        float x = (tid < 8) ? sred[tid] : -INFINITY;
        #pragma unroll
        for (int o = 4; o > 0; o >>= 1) x = fmaxf(x, __shfl_xor_sync(full, x, o));
        if (tid == 0) sred[0] = x;
    }
    __syncthreads();
    const float bmax = sred[0];
    __syncthreads();

    float lsum = 0.0f;
    #pragma unroll
    for (int e = 0; e < 8; e++) lsum += __expf(v[e] - bmax) * m[e];
    #pragma unroll
    for (int o = 16; o > 0; o >>= 1) lsum += __shfl_xor_sync(full, lsum, o);
    if ((tid & 31) == 0) sred[tid >> 5] = lsum;
    __syncthreads();
    if (tid == 0) {
        float bsum = 0.0f;
        #pragma unroll
        for (int w = 0; w < 8; w++) bsum += sred[w];
        float denom = bsum + ((bsum == 0.0f) ? 1.0f : 0.0f) + 1e-20f;
        g_rowmax[row]   = bmax;
        g_rowscale[row] = (float)mb[i] / denom;
    }
}

// ---------------------------------------------------------------------------
// Kernel 3: out[b,i,d] = sum_j exp(s[b,i,j]-max_i)*m_j*scale_i * v[b,j,d]
// Probabilities produced on the smem-load path; SGEMM-NN 128x128, BK=16.
// ---------------------------------------------------------------------------
__global__ __launch_bounds__(256) void pv_kernel(
    const float* __restrict__ v, const int* __restrict__ mask,
    float* __restrict__ out)
{
    __shared__ float Ps[16][128];
    __shared__ float Vs[16][128];

    const int b  = blockIdx.z;
    const int ti = blockIdx.y * 128;
    const int td = blockIdx.x * 128;
    const float* __restrict__ vb = v + (size_t)b * L * D;
    const float* __restrict__ srow = g_scores + ((size_t)b * L + ti) * L;
    const int* __restrict__ mb = mask + b * L;

    const int tid = threadIdx.x;
    const int lr  = tid >> 2;
    const int lc  = (tid & 3) << 2;
    const int tx  = tid & 15;
    const int ty  = tid >> 4;

    // per-thread row stats for the two P rows this thread loads
    const float rmax0 = g_rowmax[b * L + ti + lr];
    const float rscl0 = g_rowscale[b * L + ti + lr];
    const float rmax1 = g_rowmax[b * L + ti + lr + 64];
    const float rscl1 = g_rowscale[b * L + ti + lr + 64];

    const int vr = tid >> 4;          // 0..15
    const int vc = (tid & 15) * 8;    // 0..120

    float acc[8][8];
    #pragma unroll
    for (int i = 0; i < 8; i++)
        #pragma unroll
        for (int j = 0; j < 8; j++) acc[i][j] = 0.0f;

    for (int j0 = 0; j0 < L; j0 += 16) {
        float mj0 = (float)mb[j0 + lc + 0];
        float mj1 = (float)mb[j0 + lc + 1];
        float mj2 = (float)mb[j0 + lc + 2];
        float mj3 = (float)mb[j0 + lc + 3];
        #pragma unroll
        for (int h = 0; h < 2; h++) {
            int r = lr + h * 64;
            float rm = h ? rmax1 : rmax0;
            float rs = h ? rscl1 : rscl0;
            float4 sv = *(const float4*)(srow + (size_t)r * L + j0 + lc);
            Ps[lc + 0][r] = __expf(sv.x - rm) * mj0 * rs;
            Ps[lc + 1][r] = __expf(sv.y - rm) * mj1 * rs;
            Ps[lc + 2][r] = __expf(sv.z - rm) * mj2 * rs;
            Ps[lc + 3][r] = __expf(sv.w - rm) * mj3 * rs;
        }
        float4 vv0 = *(const float4*)(vb + (size_t)(j0 + vr) * D + td + vc);
        float4 vv1 = *(const float4*)(vb + (size_t)(j0 + vr) * D + td + vc + 4);
        *(float4*)&Vs[vr][vc]     = vv0;
        *(float4*)&Vs[vr][vc + 4] = vv1;
        __syncthreads();
        #pragma unroll
        for (int kk = 0; kk < 16; kk++) {
            float4 a0 = *(const float4*)&Ps[kk][ty * 4];
            float4 a1 = *(const float4*)&Ps[kk][64 + ty * 4];
            float4 b0 = *(const float4*)&Vs[kk][tx * 4];
            float4 b1 = *(const float4*)&Vs[kk][64 + tx * 4];
            float a[8]  = {a0.x, a0.y, a0.z, a0.w, a1.x, a1.y, a1.z, a1.w};
            float bb[8] = {b0.x, b0.y, b0.z, b0.w, b1.x, b1.y, b1.z, b1.w};
            #pragma unroll
            for (int i = 0; i < 8; i++)
                #pragma unroll
                for (int j = 0; j < 8; j++)
                    acc[i][j] = fmaf(a[i], bb[j], acc[i][j]);
        }
        __syncthreads();
    }

    float* ob = out + ((size_t)b * L + ti) * D + td;
    #pragma unroll
    for (int i = 0; i < 8; i++) {
        int r = (i < 4) ? (ty * 4 + i) : (64 + ty * 4 + (i - 4));
        float4 o0 = make_float4(acc[i][0], acc[i][1], acc[i][2], acc[i][3]);
        float4 o1 = make_float4(acc[i][4], acc[i][5], acc[i][6], acc[i][7]);
        *(float4*)(ob + (size_t)r * D + tx * 4)      = o0;
        *(float4*)(ob + (size_t)r * D + 64 + tx * 4) = o1;
    }
}

// ---------------------------------------------------------------------------
extern "C" void kernel_launch(void* const* d_in, const int* in_sizes, int n_in,
                              void* d_out, int out_size)
{
    const float* q    = (const float*)d_in[0];
    const float* k    = (const float*)d_in[1];
    const float* v    = (const float*)d_in[2];
    const int*   mask = (const int*)d_in[3];
    float*       out  = (float*)d_out;

    dim3 g1(L / 128, L / 128, B);
    qk_kernel<<<g1, 256>>>(q, k, mask);

    rowstats_kernel<<<B * L, 256>>>(mask);

    dim3 g3(D / 128, L / 128, B);
    pv_kernel<<<g3, 256>>>(v, mask, out);
}

// round 4
// speedup vs baseline: 2.2019x; 2.2019x over previous
#include <cuda_runtime.h>
#include <cuda_bf16.h>
#include <math.h>
#include <stdint.h>

#define B 8
#define L 2048
#define D 1024

// 128MB scratch: scores after qk, probabilities after rowstats.
__device__ float g_scores[(size_t)B * L * L];

// ---------------------------------------------------------------------------
// mma.sync wrappers (sm_80+ encodings, valid on plain compute_103 target)
// ---------------------------------------------------------------------------
__device__ __forceinline__ void mma_bf16(float c[4], uint32_t a0, uint32_t a1,
                                         uint32_t a2, uint32_t a3,
                                         uint32_t b0, uint32_t b1) {
    asm volatile(
        "mma.sync.aligned.m16n8k16.row.col.f32.bf16.bf16.f32 "
        "{%0,%1,%2,%3}, {%4,%5,%6,%7}, {%8,%9}, {%0,%1,%2,%3};"
        : "+f"(c[0]), "+f"(c[1]), "+f"(c[2]), "+f"(c[3])
        : "r"(a0), "r"(a1), "r"(a2), "r"(a3), "r"(b0), "r"(b1));
}
__device__ __forceinline__ void mma_tf32(float c[4], uint32_t a0, uint32_t a1,
                                         uint32_t a2, uint32_t a3,
                                         uint32_t b0, uint32_t b1) {
    asm volatile(
        "mma.sync.aligned.m16n8k8.row.col.f32.tf32.tf32.f32 "
        "{%0,%1,%2,%3}, {%4,%5,%6,%7}, {%8,%9}, {%0,%1,%2,%3};"
        : "+f"(c[0]), "+f"(c[1]), "+f"(c[2]), "+f"(c[3])
        : "r"(a0), "r"(a1), "r"(a2), "r"(a3), "r"(b0), "r"(b1));
}
__device__ __forceinline__ uint32_t f2tf32(float x) {
    uint32_t r; asm("cvt.rna.tf32.f32 %0, %1;" : "=r"(r) : "f"(x)); return r;
}

// ---------------------------------------------------------------------------
// Kernel 1: S = mask * (Q K^T), bf16 3-term split on mma.m16n8k16.
// CTA tile 128x128, BK=32 per stage, double-buffered smem.
// smem bf16 tiles [row][k], k-interleaved within each k16 group so that
// logical pairs (t, t+4) sit adjacent -> lds.64 fragments, 96B row stride.
// ---------------------------------------------------------------------------
#define QK_RS    96
#define QK_TILE  (128 * QK_RS)       // 12288
#define QK_STAGE (4 * QK_TILE)       // Qhi,Qlo,Khi,Klo = 49152

__global__ __launch_bounds__(256, 1) void qk_kernel(
    const float* __restrict__ q, const float* __restrict__ k,
    const int* __restrict__ mask)
{
    extern __shared__ char sm[];
    const int tid = threadIdx.x, lane = tid & 31, wid = tid >> 5;
    const int g = lane >> 2, t = lane & 3;
    const int b = blockIdx.z, ti = blockIdx.y * 128, tj = blockIdx.x * 128;
    const float* qb = q + ((size_t)b * L + ti) * D;
    const float* kb = k + ((size_t)b * L + tj) * D;

    // loader geometry: thread = (row lrow0 + 32*it, quad lq); quad = 4 floats
    const int lq = tid & 7;
    const int lrow0 = tid >> 3;
    const int lp = (2 * lq) & 7;                            // logical pair in k16 grp
    const int w0 = (lp < 4) ? (2 * lp) : (2 * (lp - 4) + 1); // phys word; w1 = w0+2
    const uint32_t stoff = (uint32_t)((lq >> 2) * 32 + w0 * 4);

    float4 qv[4], kv[4];
    float acc[4][4][4];
    #pragma unroll
    for (int a = 0; a < 4; a++)
        #pragma unroll
        for (int bb = 0; bb < 4; bb++)
            #pragma unroll
            for (int cc = 0; cc < 4; cc++) acc[a][bb][cc] = 0.0f;

    const int rm = (wid >> 2) * 64, rn = (wid & 3) * 32;

    #define QK_LOADG(c) do { \
        _Pragma("unroll") \
        for (int it = 0; it < 4; ++it) { \
            int r = lrow0 + it * 32; \
            qv[it] = *(const float4*)(qb + (size_t)r * D + (c) * 32 + lq * 4); \
            kv[it] = *(const float4*)(kb + (size_t)r * D + (c) * 32 + lq * 4); \
        } } while (0)

    #define QK_STORE(buf) do { \
        char* st = sm + (buf) * QK_STAGE; \
        _Pragma("unroll") \
        for (int it = 0; it < 4; ++it) { \
            int r = lrow0 + it * 32; \
            uint32_t base = (uint32_t)r * QK_RS + stoff; \
            float4 f = qv[it]; \
            __nv_bfloat162 h0 = __floats2bfloat162_rn(f.x, f.y); \
            __nv_bfloat162 h1 = __floats2bfloat162_rn(f.z, f.w); \
            float2 g0 = __bfloat1622float2(h0), g1 = __bfloat1622float2(h1); \
            __nv_bfloat162 l0 = __floats2bfloat162_rn(f.x - g0.x, f.y - g0.y); \
            __nv_bfloat162 l1 = __floats2bfloat162_rn(f.z - g1.x, f.w - g1.y); \
            *(uint32_t*)(st + base)               = *(uint32_t*)&h0; \
            *(uint32_t*)(st + base + 8)           = *(uint32_t*)&h1; \
            *(uint32_t*)(st + QK_TILE + base)     = *(uint32_t*)&l0; \
            *(uint32_t*)(st + QK_TILE + base + 8) = *(uint32_t*)&l1; \
            f = kv[it]; \
            h0 = __floats2bfloat162_rn(f.x, f.y); \
            h1 = __floats2bfloat162_rn(f.z, f.w); \
            g0 = __bfloat1622float2(h0); g1 = __bfloat1622float2(h1); \
            l0 = __floats2bfloat162_rn(f.x - g0.x, f.y - g0.y); \
            l1 = __floats2bfloat162_rn(f.z - g1.x, f.w - g1.y); \
            *(uint32_t*)(st + 2 * QK_TILE + base)     = *(uint32_t*)&h0; \
            *(uint32_t*)(st + 2 * QK_TILE + base + 8) = *(uint32_t*)&h1; \
            *(uint32_t*)(st + 3 * QK_TILE + base)     = *(uint32_t*)&l0; \
            *(uint32_t*)(st + 3 * QK_TILE + base + 8) = *(uint32_t*)&l1; \
        } } while (0)

    #define QK_COMPUTE(buf) do { \
        const char* Qh = sm + (buf) * QK_STAGE; \
        const char* Ql = Qh + QK_TILE; \
        const char* Kh = Qh + 2 * QK_TILE; \
        const char* Kl = Qh + 3 * QK_TILE; \
        _Pragma("unroll") \
        for (int s = 0; s < 2; ++s) { \
            const uint32_t so = (uint32_t)(s * 32 + t * 8); \
            uint2 ah[4][2], al[4][2]; \
            _Pragma("unroll") \
            for (int mt = 0; mt < 4; ++mt) { \
                uint32_t r0 = (uint32_t)(rm + mt * 16 + g) * QK_RS + so; \
                ah[mt][0] = *(const uint2*)(Qh + r0); \
                ah[mt][1] = *(const uint2*)(Qh + r0 + 8 * QK_RS); \
                al[mt][0] = *(const uint2*)(Ql + r0); \
                al[mt][1] = *(const uint2*)(Ql + r0 + 8 * QK_RS); \
            } \
            _Pragma("unroll") \
            for (int nt = 0; nt < 4; ++nt) { \
                uint32_t rb = (uint32_t)(rn + nt * 8 + g) * QK_RS + so; \
                uint2 bh = *(const uint2*)(Kh + rb); \
                uint2 bl = *(const uint2*)(Kl + rb); \
                _Pragma("unroll") \
                for (int mt = 0; mt < 4; ++mt) { \
                    mma_bf16(acc[mt][nt], ah[mt][0].x, ah[mt][1].x, ah[mt][0].y, ah[mt][1].y, bh.x, bh.y); \
                    mma_bf16(acc[mt][nt], ah[mt][0].x, ah[mt][1].x, ah[mt][0].y, ah[mt][1].y, bl.x, bl.y); \
                    mma_bf16(acc[mt][nt], al[mt][0].x, al[mt][1].x, al[mt][0].y, al[mt][1].y, bh.x, bh.y); \
                } \
            } \
        } } while (0)

    QK_LOADG(0);
    QK_STORE(0);
    __syncthreads();
    for (int c = 0; c < D / 32; ++c) {
        if (c + 1 < D / 32) QK_LOADG(c + 1);
        QK_COMPUTE(c & 1);
        if (c + 1 < D / 32) QK_STORE((c + 1) & 1);
        __syncthreads();
    }

    const int* mr = mask + b * L + ti;
    const int* mc = mask + b * L + tj;
    #pragma unroll
    for (int mt = 0; mt < 4; ++mt) {
        int r0 = rm + mt * 16 + g;
        float mi0 = (float)mr[r0], mi1 = (float)mr[r0 + 8];
        float* row0 = g_scores + ((size_t)b * L + ti + r0) * L + tj;
        float* row1 = row0 + (size_t)8 * L;
        #pragma unroll
        for (int nt = 0; nt < 4; ++nt) {
            int c0 = rn + nt * 8 + 2 * t;
            float mj0 = (float)mc[c0], mj1 = (float)mc[c0 + 1];
            *(float2*)(row0 + c0) =
                make_float2(acc[mt][nt][0] * mi0 * mj0, acc[mt][nt][1] * mi0 * mj1);
            *(float2*)(row1 + c0) =
                make_float2(acc[mt][nt][2] * mi1 * mj0, acc[mt][nt][3] * mi1 * mj1);
        }
    }
}

// ---------------------------------------------------------------------------
// Kernel 2: per-row softmax stats AND in-place rewrite of scores -> final
// probabilities p = exp(s - max) * m_j * m_i / denom.  (exp computed ONCE.)
// ---------------------------------------------------------------------------
__global__ __launch_bounds__(256) void rowstats_kernel(const int* __restrict__ mask)
{
    const int row = blockIdx.x;            // b*L + i
    const int b = row >> 11;
    const int i = row & (L - 1);
    float* s = g_scores + (size_t)row * L;
    const int* mb = mask + b * L;
    const int tid = threadIdx.x;
    const int base = tid * 8;

    float v[8], m[8];
    float4 v0 = *(const float4*)(s + base);
    float4 v1 = *(const float4*)(s + base + 4);
    int4 m0 = *(const int4*)(mb + base);
    int4 m1 = *(const int4*)(mb + base + 4);
    v[0]=v0.x; v[1]=v0.y; v[2]=v0.z; v[3]=v0.w;
    v[4]=v1.x; v[5]=v1.y; v[6]=v1.z; v[7]=v1.w;
    m[0]=(float)m0.x; m[1]=(float)m0.y; m[2]=(float)m0.z; m[3]=(float)m0.w;
    m[4]=(float)m1.x; m[5]=(float)m1.y; m[6]=(float)m1.z; m[7]=(float)m1.w;

    __shared__ float sredA[8], sredB[8];
    const unsigned full = 0xffffffffu;

    float lmax = v[0];
    #pragma unroll
    for (int e = 1; e < 8; e++) lmax = fmaxf(lmax, v[e]);
    #pragma unroll
    for (int o = 16; o > 0; o >>= 1) lmax = fmaxf(lmax, __shfl_xor_sync(full, lmax, o));
    if ((tid & 31) == 0) sredA[tid >> 5] = lmax;
    __syncthreads();
    float bmax = sredA[0];
    #pragma unroll
    for (int w = 1; w < 8; w++) bmax = fmaxf(bmax, sredA[w]);

    float p[8];
    float lsum = 0.0f;
    #pragma unroll
    for (int e = 0; e < 8; e++) { p[e] = __expf(v[e] - bmax) * m[e]; lsum += p[e]; }
    #pragma unroll
    for (int o = 16; o > 0; o >>= 1) lsum += __shfl_xor_sync(full, lsum, o);
    if ((tid & 31) == 0) sredB[tid >> 5] = lsum;
    __syncthreads();
    float bsum = 0.0f;
    #pragma unroll
    for (int w = 0; w < 8; w++) bsum += sredB[w];

    const float denom = bsum + ((bsum == 0.0f) ? 1.0f : 0.0f) + 1e-20f;
    const float scale = (float)mb[i] / denom;

    float4 o0 = make_float4(p[0]*scale, p[1]*scale, p[2]*scale, p[3]*scale);
    float4 o1 = make_float4(p[4]*scale, p[5]*scale, p[6]*scale, p[7]*scale);
    *(float4*)(s + base)     = o0;
    *(float4*)(s + base + 4) = o1;
}

// ---------------------------------------------------------------------------
// Kernel 3: O = P V, tf32 mma.m16n8k8.  CTA tile 128(i) x 128(d), BK=32(j).
// P: tf32, k-interleaved, 160B row stride (lds.64 A-frags).
// V: tf32, row-major [j][d], 544B row stride (lds.32 B-frags bank-perfect,
//    coalesced 16B stores on fill — no transpose needed).
// ---------------------------------------------------------------------------
#define PV_PRS   160
#define PV_PTILE (128 * PV_PRS)          // 20480
#define PV_VRS   544
#define PV_VTILE (32 * PV_VRS)           // 17408
#define PV_STAGE (PV_PTILE + PV_VTILE)   // 37888

__global__ __launch_bounds__(256, 1) void pv_kernel(
    const float* __restrict__ v, float* __restrict__ out)
{
    extern __shared__ char sm[];
    const int tid = threadIdx.x, lane = tid & 31, wid = tid >> 5;
    const int g = lane >> 2, t = lane & 3;
    const int b = blockIdx.z, ti = blockIdx.y * 128, td = blockIdx.x * 128;
    const float* pb = g_scores + ((size_t)b * L + ti) * L;
    const float* vb = v + (size_t)b * L * D + td;

    const int lq = tid & 7;
    const int lrow0 = tid >> 3;
    const uint32_t pbase_off = (uint32_t)((lq >> 1) * 32 + (lq & 1) * 4);

    float4 pv4[4], vv4[4];
    float acc[4][4][4];
    #pragma unroll
    for (int a = 0; a < 4; a++)
        #pragma unroll
        for (int bb = 0; bb < 4; bb++)
            #pragma unroll
            for (int cc = 0; cc < 4; cc++) acc[a][bb][cc] = 0.0f;

    const int rm = (wid >> 2) * 64, rn = (wid & 3) * 32;

    #define PV_LOADG(c) do { \
        const int j0 = (c) * 32; \
        _Pragma("unroll") \
        for (int it = 0; it < 4; ++it) { \
            pv4[it] = *(const float4*)(pb + (size_t)(lrow0 + it * 32) * L + j0 + lq * 4); \
            vv4[it] = *(const float4*)(vb + (size_t)(j0 + lrow0) * D + (lq + 8 * it) * 4); \
        } } while (0)

    #define PV_STORE(buf) do { \
        char* st = sm + (buf) * PV_STAGE; \
        _Pragma("unroll") \
        for (int it = 0; it < 4; ++it) { \
            uint32_t base = (uint32_t)(lrow0 + it * 32) * PV_PRS + pbase_off; \
            float4 f = pv4[it]; \
            *(uint32_t*)(st + base)      = f2tf32(f.x); \
            *(uint32_t*)(st + base + 8)  = f2tf32(f.y); \
            *(uint32_t*)(st + base + 16) = f2tf32(f.z); \
            *(uint32_t*)(st + base + 24) = f2tf32(f.w); \
        } \
        char* vt = st + PV_PTILE; \
        _Pragma("unroll") \
        for (int it = 0; it < 4; ++it) { \
            uint4 u; \
            u.x = f2tf32(vv4[it].x); u.y = f2tf32(vv4[it].y); \
            u.z = f2tf32(vv4[it].z); u.w = f2tf32(vv4[it].w); \
            *(uint4*)(vt + (uint32_t)lrow0 * PV_VRS + (lq + 8 * it) * 16) = u; \
        } } while (0)

    #define PV_COMPUTE(buf) do { \
        const char* P = sm + (buf) * PV_STAGE; \
        const char* Vt = P + PV_PTILE; \
        _Pragma("unroll") \
        for (int s = 0; s < 4; ++s) { \
            const uint32_t so = (uint32_t)(s * 32 + t * 8); \
            uint2 a[4][2]; \
            _Pragma("unroll") \
            for (int mt = 0; mt < 4; ++mt) { \
                uint32_t r0 = (uint32_t)(rm + mt * 16 + g) * PV_PRS + so; \
                a[mt][0] = *(const uint2*)(P + r0); \
                a[mt][1] = *(const uint2*)(P + r0 + 8 * PV_PRS); \
            } \
            _Pragma("unroll") \
            for (int nt = 0; nt < 4; ++nt) { \
                uint32_t col = (uint32_t)(rn + nt * 8 + g) * 4; \
                uint32_t b0 = *(const uint32_t*)(Vt + (uint32_t)(s * 8 + t) * PV_VRS + col); \
                uint32_t b1 = *(const uint32_t*)(Vt + (uint32_t)(s * 8 + t + 4) * PV_VRS + col); \
                _Pragma("unroll") \
                for (int mt = 0; mt < 4; ++mt) \
                    mma_tf32(acc[mt][nt], a[mt][0].x, a[mt][1].x, a[mt][0].y, a[mt][1].y, b0, b1); \
            } \
        } } while (0)

    PV_LOADG(0);
    PV_STORE(0);
    __syncthreads();
    for (int c = 0; c < L / 32; ++c) {
        if (c + 1 < L / 32) PV_LOADG(c + 1);
        PV_COMPUTE(c & 1);
        if (c + 1 < L / 32) PV_STORE((c + 1) & 1);
        __syncthreads();
    }

    #pragma unroll
    for (int mt = 0; mt < 4; ++mt) {
        int r0 = rm + mt * 16 + g;
        float* row0 = out + ((size_t)b * L + ti + r0) * D + td;
        float* row1 = row0 + (size_t)8 * D;
        #pragma unroll
        for (int nt = 0; nt < 4; ++nt) {
            int c0 = rn + nt * 8 + 2 * t;
            *(float2*)(row0 + c0) = make_float2(acc[mt][nt][0], acc[mt][nt][1]);
            *(float2*)(row1 + c0) = make_float2(acc[mt][nt][2], acc[mt][nt][3]);
        }
    }
}

// ---------------------------------------------------------------------------
extern "C" void kernel_launch(void* const* d_in, const int* in_sizes, int n_in,
                              void* d_out, int out_size)
{
    const float* q    = (const float*)d_in[0];
    const float* k    = (const float*)d_in[1];
    const float* v    = (const float*)d_in[2];
    const int*   mask = (const int*)d_in[3];
    float*       out  = (float*)d_out;

    cudaFuncSetAttribute(qk_kernel, cudaFuncAttributeMaxDynamicSharedMemorySize, 2 * QK_STAGE);
    cudaFuncSetAttribute(pv_kernel, cudaFuncAttributeMaxDynamicSharedMemorySize, 2 * PV_STAGE);

    dim3 g1(L / 128, L / 128, B);
    qk_kernel<<<g1, 256, 2 * QK_STAGE>>>(q, k, mask);

    rowstats_kernel<<<B * L, 256>>>(mask);

    dim3 g3(D / 128, L / 128, B);
    pv_kernel<<<g3, 256, 2 * PV_STAGE>>>(v, out);
}

// round 5
// speedup vs baseline: 2.5406x; 1.1538x over previous
#include <cuda_runtime.h>
#include <cuda_bf16.h>
#include <cuda_fp16.h>
#include <math.h>
#include <stdint.h>

#define B 8
#define L 2048
#define D 1024

// scratch
__device__ float         g_scores[(size_t)B * L * L];   // raw scores (qk -> rowstats)
__device__ __half        g_probs[(size_t)B * L * L];    // final probabilities (rowstats -> pv)
__device__ __nv_bfloat16 g_qh[(size_t)B * L * D];
__device__ __nv_bfloat16 g_ql[(size_t)B * L * D];
__device__ __nv_bfloat16 g_kh[(size_t)B * L * D];
__device__ __nv_bfloat16 g_kl[(size_t)B * L * D];
__device__ __half        g_vt[(size_t)B * L * D];       // V transposed: [b][d][j]

// ---------------------------------------------------------------------------
// helpers
// ---------------------------------------------------------------------------
__device__ __forceinline__ uint32_t smem_u32(const void* p) {
    uint32_t a;
    asm("{ .reg .u64 t; cvta.to.shared.u64 t, %1; cvt.u32.u64 %0, t; }" : "=r"(a) : "l"(p));
    return a;
}
__device__ __forceinline__ void cp16(uint32_t dst, const void* src) {
    asm volatile("cp.async.cg.shared.global [%0], [%1], 16;" :: "r"(dst), "l"(src) : "memory");
}
#define CP_COMMIT() asm volatile("cp.async.commit_group;" ::: "memory")
#define CP_WAIT(n)  asm volatile("cp.async.wait_group %0;" :: "n"(n) : "memory")

__device__ __forceinline__ void mma_bf16(float c[4], uint32_t a0, uint32_t a1,
                                         uint32_t a2, uint32_t a3,
                                         uint32_t b0, uint32_t b1) {
    asm volatile(
        "mma.sync.aligned.m16n8k16.row.col.f32.bf16.bf16.f32 "
        "{%0,%1,%2,%3}, {%4,%5,%6,%7}, {%8,%9}, {%0,%1,%2,%3};"
        : "+f"(c[0]), "+f"(c[1]), "+f"(c[2]), "+f"(c[3])
        : "r"(a0), "r"(a1), "r"(a2), "r"(a3), "r"(b0), "r"(b1));
}
__device__ __forceinline__ void mma_f16(float c[4], uint32_t a0, uint32_t a1,
                                        uint32_t a2, uint32_t a3,
                                        uint32_t b0, uint32_t b1) {
    asm volatile(
        "mma.sync.aligned.m16n8k16.row.col.f32.f16.f16.f32 "
        "{%0,%1,%2,%3}, {%4,%5,%6,%7}, {%8,%9}, {%0,%1,%2,%3};"
        : "+f"(c[0]), "+f"(c[1]), "+f"(c[2]), "+f"(c[3])
        : "r"(a0), "r"(a1), "r"(a2), "r"(a3), "r"(b0), "r"(b1));
}

// ---------------------------------------------------------------------------
// Prep 1: q,k f32 -> bf16 hi/lo, k-pair-interleaved within each k16 group
// (phys unit order per 32B group: p0,p4,p1,p5,p2,p6,p3,p7).
// ---------------------------------------------------------------------------
__global__ __launch_bounds__(256) void prep_qk_kernel(
    const float* __restrict__ q, const float* __restrict__ k)
{
    const float* src = blockIdx.y ? k : q;
    __nv_bfloat16* dh = blockIdx.y ? g_kh : g_qh;
    __nv_bfloat16* dl = blockIdx.y ? g_kl : g_ql;
    size_t gi = (size_t)blockIdx.x * 256 + threadIdx.x;   // 16-elem group id
    const float* s = src + gi * 16;

    uint32_t h[8], l[8];
    #pragma unroll
    for (int qd = 0; qd < 4; ++qd) {
        float4 x = *(const float4*)(s + 4 * qd);
        __nv_bfloat162 h0 = __floats2bfloat162_rn(x.x, x.y);
        __nv_bfloat162 h1 = __floats2bfloat162_rn(x.z, x.w);
        float2 b0 = __bfloat1622float2(h0), b1 = __bfloat1622float2(h1);
        __nv_bfloat162 l0 = __floats2bfloat162_rn(x.x - b0.x, x.y - b0.y);
        __nv_bfloat162 l1 = __floats2bfloat162_rn(x.z - b1.x, x.w - b1.y);
        h[2*qd] = *(uint32_t*)&h0; h[2*qd+1] = *(uint32_t*)&h1;
        l[2*qd] = *(uint32_t*)&l0; l[2*qd+1] = *(uint32_t*)&l1;
    }
    *(uint4*)(dh + gi * 16)     = make_uint4(h[0], h[4], h[1], h[5]);
    *(uint4*)(dh + gi * 16 + 8) = make_uint4(h[2], h[6], h[3], h[7]);
    *(uint4*)(dl + gi * 16)     = make_uint4(l[0], l[4], l[1], l[5]);
    *(uint4*)(dl + gi * 16 + 8) = make_uint4(l[2], l[6], l[3], l[7]);
}

// ---------------------------------------------------------------------------
// Prep 2: V f32 [b][j][d] -> fp16 transposed [b][d][j]
// ---------------------------------------------------------------------------
__global__ __launch_bounds__(256) void prep_v_kernel(const float* __restrict__ v)
{
    __shared__ __half t[32][72];
    const int b = blockIdx.z, d0 = blockIdx.y * 32, j0 = blockIdx.x * 64;
    const int tid = threadIdx.x;
    const int dd = tid & 31, jw = tid >> 5;
    #pragma unroll
    for (int it = 0; it < 8; ++it) {
        int jj = jw + it * 8;
        float x = v[((size_t)b * L + j0 + jj) * D + d0 + dd];
        t[dd][jj] = __float2half_rn(x);
    }
    __syncthreads();
    const int row = tid >> 3, c8 = (tid & 7) * 8;
    uint32_t u[4];
    #pragma unroll
    for (int e = 0; e < 4; ++e) {
        __half2 hp; hp.x = t[row][c8 + 2*e]; hp.y = t[row][c8 + 2*e + 1];
        u[e] = *(uint32_t*)&hp;
    }
    *(uint4*)(g_vt + ((size_t)b * D + d0 + row) * L + j0 + c8) =
        make_uint4(u[0], u[1], u[2], u[3]);
}

// ---------------------------------------------------------------------------
// Kernel 1: raw S = Q K^T, bf16 3-term split, cp.async 3-stage pipeline.
// CTA tile 128x128, BK=32. smem rows: 64B data @ 96B stride (lds.64 frags).
// ---------------------------------------------------------------------------
#define QK_RS    96
#define QK_TILE  (128 * QK_RS)       // 12288
#define QK_STAGE (4 * QK_TILE)       // 49152

__global__ __launch_bounds__(256, 1) void qk_kernel()
{
    extern __shared__ char sm[];
    const uint32_t smbase = smem_u32(sm);
    const int tid = threadIdx.x, lane = tid & 31, wid = tid >> 5;
    const int g = lane >> 2, t = lane & 3;
    const int b = blockIdx.z, ti = blockIdx.y * 128, tj = blockIdx.x * 128;

    const __nv_bfloat16* qh = g_qh + ((size_t)b * L + ti) * D;
    const __nv_bfloat16* ql = g_ql + ((size_t)b * L + ti) * D;
    const __nv_bfloat16* kh = g_kh + ((size_t)b * L + tj) * D;
    const __nv_bfloat16* kl = g_kl + ((size_t)b * L + tj) * D;

    float acc[4][4][4];
    #pragma unroll
    for (int a = 0; a < 4; a++)
        #pragma unroll
        for (int bb = 0; bb < 4; bb++)
            #pragma unroll
            for (int cc = 0; cc < 4; cc++) acc[a][bb][cc] = 0.0f;

    const int rm = (wid >> 2) * 64, rn = (wid & 3) * 32;

    #define QK_LOAD(c, st) do { \
        uint32_t sb = smbase + (st) * QK_STAGE; \
        _Pragma("unroll") \
        for (int e = 0; e < 2; ++e) { \
            int idx = 2 * tid + e; \
            int r = idx >> 2, sg = idx & 3; \
            uint32_t doff = (uint32_t)r * QK_RS + sg * 16; \
            size_t goff = (size_t)r * D + (size_t)(c) * 32 + sg * 8; \
            cp16(sb + doff,               qh + goff); \
            cp16(sb + QK_TILE + doff,     ql + goff); \
            cp16(sb + 2 * QK_TILE + doff, kh + goff); \
            cp16(sb + 3 * QK_TILE + doff, kl + goff); \
        } } while (0)

    #define QK_COMPUTE(buf) do { \
        const char* Qh = sm + (buf) * QK_STAGE; \
        const char* Ql = Qh + QK_TILE; \
        const char* Kh = Qh + 2 * QK_TILE; \
        const char* Kl = Qh + 3 * QK_TILE; \
        _Pragma("unroll") \
        for (int s = 0; s < 2; ++s) { \
            const uint32_t so = (uint32_t)(s * 32 + t * 8); \
            uint2 ah[4][2], al[4][2]; \
            _Pragma("unroll") \
            for (int mt = 0; mt < 4; ++mt) { \
                uint32_t r0 = (uint32_t)(rm + mt * 16 + g) * QK_RS + so; \
                ah[mt][0] = *(const uint2*)(Qh + r0); \
                ah[mt][1] = *(const uint2*)(Qh + r0 + 8 * QK_RS); \
                al[mt][0] = *(const uint2*)(Ql + r0); \
                al[mt][1] = *(const uint2*)(Ql + r0 + 8 * QK_RS); \
            } \
            _Pragma("unroll") \
            for (int nt = 0; nt < 4; ++nt) { \
                uint32_t rb = (uint32_t)(rn + nt * 8 + g) * QK_RS + so; \
                uint2 bh = *(const uint2*)(Kh + rb); \
                uint2 bl = *(const uint2*)(Kl + rb); \
                _Pragma("unroll") \
                for (int mt = 0; mt < 4; ++mt) { \
                    mma_bf16(acc[mt][nt], ah[mt][0].x, ah[mt][1].x, ah[mt][0].y, ah[mt][1].y, bh.x, bh.y); \
                    mma_bf16(acc[mt][nt], ah[mt][0].x, ah[mt][1].x, ah[mt][0].y, ah[mt][1].y, bl.x, bl.y); \
                    mma_bf16(acc[mt][nt], al[mt][0].x, al[mt][1].x, al[mt][0].y, al[mt][1].y, bh.x, bh.y); \
                } \
            } \
        } } while (0)

    QK_LOAD(0, 0); CP_COMMIT();
    QK_LOAD(1, 1); CP_COMMIT();
    for (int c = 0; c < D / 32; ++c) {
        CP_WAIT(1);
        __syncthreads();
        if (c + 2 < D / 32) QK_LOAD(c + 2, (c + 2) % 3);
        CP_COMMIT();
        QK_COMPUTE(c % 3);
    }

    // raw score writeback (masking happens in rowstats)
    #pragma unroll
    for (int mt = 0; mt < 4; ++mt) {
        int r0 = rm + mt * 16 + g;
        float* row0 = g_scores + ((size_t)b * L + ti + r0) * L + tj;
        float* row1 = row0 + (size_t)8 * L;
        #pragma unroll
        for (int nt = 0; nt < 4; ++nt) {
            int c0 = rn + nt * 8 + 2 * t;
            *(float2*)(row0 + c0) = make_float2(acc[mt][nt][0], acc[mt][nt][1]);
            *(float2*)(row1 + c0) = make_float2(acc[mt][nt][2], acc[mt][nt][3]);
        }
    }
}

// ---------------------------------------------------------------------------
// Kernel 2: masking + softmax stats + write final probabilities as fp16.
// p = exp(s*mi*mj - max) * mi*mj / denom, denom per reference semantics.
// ---------------------------------------------------------------------------
__global__ __launch_bounds__(256) void rowstats_kernel(const int* __restrict__ mask)
{
    const int row = blockIdx.x;            // b*L + i
    const int b = row >> 11;
    const int i = row & (L - 1);
    const float* s = g_scores + (size_t)row * L;
    const int* mb = mask + b * L;
    const int tid = threadIdx.x;
    const int base = tid * 8;
    const float mi = (float)mb[i];

    float v[8], m[8];
    float4 v0 = *(const float4*)(s + base);
    float4 v1 = *(const float4*)(s + base + 4);
    int4 m0 = *(const int4*)(mb + base);
    int4 m1 = *(const int4*)(mb + base + 4);
    v[0]=v0.x; v[1]=v0.y; v[2]=v0.z; v[3]=v0.w;
    v[4]=v1.x; v[5]=v1.y; v[6]=v1.z; v[7]=v1.w;
    m[0]=(float)m0.x*mi; m[1]=(float)m0.y*mi; m[2]=(float)m0.z*mi; m[3]=(float)m0.w*mi;
    m[4]=(float)m1.x*mi; m[5]=(float)m1.y*mi; m[6]=(float)m1.z*mi; m[7]=(float)m1.w*mi;

    #pragma unroll
    for (int e = 0; e < 8; e++) v[e] *= m[e];     // masked scores

    __shared__ float sredA[8], sredB[8];
    const unsigned full = 0xffffffffu;

    float lmax = v[0];
    #pragma unroll
    for (int e = 1; e < 8; e++) lmax = fmaxf(lmax, v[e]);
    #pragma unroll
    for (int o = 16; o > 0; o >>= 1) lmax = fmaxf(lmax, __shfl_xor_sync(full, lmax, o));
    if ((tid & 31) == 0) sredA[tid >> 5] = lmax;
    __syncthreads();
    float bmax = sredA[0];
    #pragma unroll
    for (int w = 1; w < 8; w++) bmax = fmaxf(bmax, sredA[w]);

    float p[8];
    float lsum = 0.0f;
    #pragma unroll
    for (int e = 0; e < 8; e++) { p[e] = __expf(v[e] - bmax) * m[e]; lsum += p[e]; }
    #pragma unroll
    for (int o = 16; o > 0; o >>= 1) lsum += __shfl_xor_sync(full, lsum, o);
    if ((tid & 31) == 0) sredB[tid >> 5] = lsum;
    __syncthreads();
    float bsum = 0.0f;
    #pragma unroll
    for (int w = 0; w < 8; w++) bsum += sredB[w];

    const float denom = bsum + ((bsum == 0.0f) ? 1.0f : 0.0f) + 1e-20f;
    const float scale = 1.0f / denom;

    uint32_t u[4];
    #pragma unroll
    for (int e = 0; e < 4; ++e) {
        __half2 hp = __floats2half2_rn(p[2*e] * scale, p[2*e+1] * scale);
        u[e] = *(uint32_t*)&hp;
    }
    *(uint4*)(g_probs + (size_t)row * L + base) = make_uint4(u[0], u[1], u[2], u[3]);
}

// ---------------------------------------------------------------------------
// Kernel 3: O = P V, fp16 mma.m16n8k16.  CTA tile 128(i) x 128(d), BK=32(j).
// P [i][j] and Vt [d][j] fp16 in smem: 64B data @ 80B stride (lds.32 frags).
// ---------------------------------------------------------------------------
#define PV_RS    80
#define PV_TILE  (128 * PV_RS)       // 10240
#define PV_STAGE (2 * PV_TILE)       // 20480

__global__ __launch_bounds__(256, 2) void pv_kernel(float* __restrict__ out)
{
    extern __shared__ char sm[];
    const uint32_t smbase = smem_u32(sm);
    const int tid = threadIdx.x, lane = tid & 31, wid = tid >> 5;
    const int g = lane >> 2, t = lane & 3;
    const int b = blockIdx.z, ti = blockIdx.y * 128, td = blockIdx.x * 128;

    const __half* pb  = g_probs + ((size_t)b * L + ti) * L;
    const __half* vtb = g_vt + ((size_t)b * D + td) * L;

    float acc[4][4][4];
    #pragma unroll
    for (int a = 0; a < 4; a++)
        #pragma unroll
        for (int bb = 0; bb < 4; bb++)
            #pragma unroll
            for (int cc = 0; cc < 4; cc++) acc[a][bb][cc] = 0.0f;

    const int rm = (wid >> 2) * 64, rn = (wid & 3) * 32;

    #define PV_LOAD(c, st) do { \
        uint32_t sb = smbase + (st) * PV_STAGE; \
        _Pragma("unroll") \
        for (int e = 0; e < 2; ++e) { \
            int idx = 2 * tid + e; \
            int r = idx >> 2, sg = idx & 3; \
            uint32_t doff = (uint32_t)r * PV_RS + sg * 16; \
            size_t goff = (size_t)r * L + (size_t)(c) * 32 + sg * 8; \
            cp16(sb + doff,           pb  + goff); \
            cp16(sb + PV_TILE + doff, vtb + goff); \
        } } while (0)

    #define PV_COMPUTE(buf) do { \
        const char* Pt = sm + (buf) * PV_STAGE; \
        const char* Vt = Pt + PV_TILE; \
        _Pragma("unroll") \
        for (int s = 0; s < 2; ++s) { \
            const uint32_t so = (uint32_t)(32 * s + 4 * t); \
            uint32_t a0[4], a1[4], a2[4], a3[4]; \
            _Pragma("unroll") \
            for (int mt = 0; mt < 4; ++mt) { \
                uint32_t r0 = (uint32_t)(rm + mt * 16 + g) * PV_RS + so; \
                a0[mt] = *(const uint32_t*)(Pt + r0); \
                a2[mt] = *(const uint32_t*)(Pt + r0 + 16); \
                a1[mt] = *(const uint32_t*)(Pt + r0 + 8 * PV_RS); \
                a3[mt] = *(const uint32_t*)(Pt + r0 + 8 * PV_RS + 16); \
            } \
            _Pragma("unroll") \
            for (int nt = 0; nt < 4; ++nt) { \
                uint32_t rb = (uint32_t)(rn + nt * 8 + g) * PV_RS + so; \
                uint32_t b0 = *(const uint32_t*)(Vt + rb); \
                uint32_t b1 = *(const uint32_t*)(Vt + rb + 16); \
                _Pragma("unroll") \
                for (int mt = 0; mt < 4; ++mt) \
                    mma_f16(acc[mt][nt], a0[mt], a1[mt], a2[mt], a3[mt], b0, b1); \
            } \
        } } while (0)

    PV_LOAD(0, 0); CP_COMMIT();
    PV_LOAD(1, 1); CP_COMMIT();
    for (int c = 0; c < L / 32; ++c) {
        CP_WAIT(1);
        __syncthreads();
        if (c + 2 < L / 32) PV_LOAD(c + 2, (c + 2) % 3);
        CP_COMMIT();
        PV_COMPUTE(c % 3);
    }

    #pragma unroll
    for (int mt = 0; mt < 4; ++mt) {
        int r0 = rm + mt * 16 + g;
        float* row0 = out + ((size_t)b * L + ti + r0) * D + td;
        float* row1 = row0 + (size_t)8 * D;
        #pragma unroll
        for (int nt = 0; nt < 4; ++nt) {
            int c0 = rn + nt * 8 + 2 * t;
            *(float2*)(row0 + c0) = make_float2(acc[mt][nt][0], acc[mt][nt][1]);
            *(float2*)(row1 + c0) = make_float2(acc[mt][nt][2], acc[mt][nt][3]);
        }
    }
}

// ---------------------------------------------------------------------------
extern "C" void kernel_launch(void* const* d_in, const int* in_sizes, int n_in,
                              void* d_out, int out_size)
{
    const float* q    = (const float*)d_in[0];
    const float* k    = (const float*)d_in[1];
    const float* v    = (const float*)d_in[2];
    const int*   mask = (const int*)d_in[3];
    float*       out  = (float*)d_out;

    cudaFuncSetAttribute(qk_kernel, cudaFuncAttributeMaxDynamicSharedMemorySize, 3 * QK_STAGE);
    cudaFuncSetAttribute(pv_kernel, cudaFuncAttributeMaxDynamicSharedMemorySize, 3 * PV_STAGE);

    prep_qk_kernel<<<dim3((B * L * D / 16) / 256, 2, 1), 256>>>(q, k);
    prep_v_kernel<<<dim3(L / 64, D / 32, B), 256>>>(v);

    dim3 g1(L / 128, L / 128, B);
    qk_kernel<<<g1, 256, 3 * QK_STAGE>>>();

    rowstats_kernel<<<B * L, 256>>>(mask);

    dim3 g3(D / 128, L / 128, B);
    pv_kernel<<<g3, 256, 3 * PV_STAGE>>>(out);
}

// round 6
// speedup vs baseline: 2.7999x; 1.1021x over previous
#include <cuda_runtime.h>
#include <cuda_bf16.h>
#include <cuda_fp16.h>
#include <math.h>
#include <stdint.h>

#define B 8
#define L 2048
#define D 1024

// scratch
__device__ float         g_scores[(size_t)B * L * L];   // raw scores (qk -> rowstats)
__device__ __half        g_probs[(size_t)B * L * L];    // final probabilities (rowstats -> pv)
__device__ __nv_bfloat16 g_qh[(size_t)B * L * D];
__device__ __nv_bfloat16 g_ql[(size_t)B * L * D];
__device__ __nv_bfloat16 g_kh[(size_t)B * L * D];
__device__ __nv_bfloat16 g_kl[(size_t)B * L * D];
__device__ __half        g_vt[(size_t)B * L * D];       // V transposed: [b][d][j]

// ---------------------------------------------------------------------------
// helpers
// ---------------------------------------------------------------------------
__device__ __forceinline__ uint32_t smem_u32(const void* p) {
    uint32_t a;
    asm("{ .reg .u64 t; cvta.to.shared.u64 t, %1; cvt.u32.u64 %0, t; }" : "=r"(a) : "l"(p));
    return a;
}
__device__ __forceinline__ void cp16(uint32_t dst, const void* src) {
    asm volatile("cp.async.cg.shared.global [%0], [%1], 16;" :: "r"(dst), "l"(src) : "memory");
}
#define CP_COMMIT() asm volatile("cp.async.commit_group;" ::: "memory")
#define CP_WAIT(n)  asm volatile("cp.async.wait_group %0;" :: "n"(n) : "memory")

__device__ __forceinline__ void mma_bf16(float c[4], uint32_t a0, uint32_t a1,
                                         uint32_t a2, uint32_t a3,
                                         uint32_t b0, uint32_t b1) {
    asm volatile(
        "mma.sync.aligned.m16n8k16.row.col.f32.bf16.bf16.f32 "
        "{%0,%1,%2,%3}, {%4,%5,%6,%7}, {%8,%9}, {%0,%1,%2,%3};"
        : "+f"(c[0]), "+f"(c[1]), "+f"(c[2]), "+f"(c[3])
        : "r"(a0), "r"(a1), "r"(a2), "r"(a3), "r"(b0), "r"(b1));
}
__device__ __forceinline__ void mma_f16(float c[4], uint32_t a0, uint32_t a1,
                                        uint32_t a2, uint32_t a3,
                                        uint32_t b0, uint32_t b1) {
    asm volatile(
        "mma.sync.aligned.m16n8k16.row.col.f32.f16.f16.f32 "
        "{%0,%1,%2,%3}, {%4,%5,%6,%7}, {%8,%9}, {%0,%1,%2,%3};"
        : "+f"(c[0]), "+f"(c[1]), "+f"(c[2]), "+f"(c[3])
        : "r"(a0), "r"(a1), "r"(a2), "r"(a3), "r"(b0), "r"(b1));
}

// ---------------------------------------------------------------------------
// Prep 1: q,k f32 -> bf16 hi/lo, k-pair-interleaved within each k16 group.
// ---------------------------------------------------------------------------
__global__ __launch_bounds__(256) void prep_qk_kernel(
    const float* __restrict__ q, const float* __restrict__ k)
{
    const float* src = blockIdx.y ? k : q;
    __nv_bfloat16* dh = blockIdx.y ? g_kh : g_qh;
    __nv_bfloat16* dl = blockIdx.y ? g_kl : g_ql;
    size_t gi = (size_t)blockIdx.x * 256 + threadIdx.x;   // 16-elem group id
    const float* s = src + gi * 16;

    uint32_t h[8], l[8];
    #pragma unroll
    for (int qd = 0; qd < 4; ++qd) {
        float4 x = *(const float4*)(s + 4 * qd);
        __nv_bfloat162 h0 = __floats2bfloat162_rn(x.x, x.y);
        __nv_bfloat162 h1 = __floats2bfloat162_rn(x.z, x.w);
        float2 b0 = __bfloat1622float2(h0), b1 = __bfloat1622float2(h1);
        __nv_bfloat162 l0 = __floats2bfloat162_rn(x.x - b0.x, x.y - b0.y);
        __nv_bfloat162 l1 = __floats2bfloat162_rn(x.z - b1.x, x.w - b1.y);
        h[2*qd] = *(uint32_t*)&h0; h[2*qd+1] = *(uint32_t*)&h1;
        l[2*qd] = *(uint32_t*)&l0; l[2*qd+1] = *(uint32_t*)&l1;
    }
    *(uint4*)(dh + gi * 16)     = make_uint4(h[0], h[4], h[1], h[5]);
    *(uint4*)(dh + gi * 16 + 8) = make_uint4(h[2], h[6], h[3], h[7]);
    *(uint4*)(dl + gi * 16)     = make_uint4(l[0], l[4], l[1], l[5]);
    *(uint4*)(dl + gi * 16 + 8) = make_uint4(l[2], l[6], l[3], l[7]);
}

// ---------------------------------------------------------------------------
// Prep 2: V f32 [b][j][d] -> fp16 transposed [b][d][j]
// ---------------------------------------------------------------------------
__global__ __launch_bounds__(256) void prep_v_kernel(const float* __restrict__ v)
{
    __shared__ __half t[32][72];
    const int b = blockIdx.z, d0 = blockIdx.y * 32, j0 = blockIdx.x * 64;
    const int tid = threadIdx.x;
    const int dd = tid & 31, jw = tid >> 5;
    #pragma unroll
    for (int it = 0; it < 8; ++it) {
        int jj = jw + it * 8;
        float x = v[((size_t)b * L + j0 + jj) * D + d0 + dd];
        t[dd][jj] = __float2half_rn(x);
    }
    __syncthreads();
    const int row = tid >> 3, c8 = (tid & 7) * 8;
    uint32_t u[4];
    #pragma unroll
    for (int e = 0; e < 4; ++e) {
        __half2 hp; hp.x = t[row][c8 + 2*e]; hp.y = t[row][c8 + 2*e + 1];
        u[e] = *(uint32_t*)&hp;
    }
    *(uint4*)(g_vt + ((size_t)b * D + d0 + row) * L + j0 + c8) =
        make_uint4(u[0], u[1], u[2], u[3]);
}

// ---------------------------------------------------------------------------
// Kernel 1: raw S = Q K^T, bf16 3-term split.
// 2-stage double buffer, load-after-sync, wait_group(0): one sync per stage.
// 2 CTAs/SM (96KB smem, <=128 regs).
// ---------------------------------------------------------------------------
#define QK_RS    96
#define QK_TILE  (128 * QK_RS)       // 12288
#define QK_STAGE (4 * QK_TILE)       // 49152
#define QK_NC    (D / 32)            // 32 stages

__global__ __launch_bounds__(256, 2) void qk_kernel()
{
    extern __shared__ char sm[];
    const uint32_t smbase = smem_u32(sm);
    const int tid = threadIdx.x, lane = tid & 31, wid = tid >> 5;
    const int g = lane >> 2, t = lane & 3;
    const int b = blockIdx.z, ti = blockIdx.y * 128, tj = blockIdx.x * 128;

    const __nv_bfloat16* qh = g_qh + ((size_t)b * L + ti) * D;
    const __nv_bfloat16* ql = g_ql + ((size_t)b * L + ti) * D;
    const __nv_bfloat16* kh = g_kh + ((size_t)b * L + tj) * D;
    const __nv_bfloat16* kl = g_kl + ((size_t)b * L + tj) * D;

    float acc[4][4][4];
    #pragma unroll
    for (int a = 0; a < 4; a++)
        #pragma unroll
        for (int bb = 0; bb < 4; bb++)
            #pragma unroll
            for (int cc = 0; cc < 4; cc++) acc[a][bb][cc] = 0.0f;

    const int rm = (wid >> 2) * 64, rn = (wid & 3) * 32;

    #define QK_LOAD(c, st) do { \
        uint32_t sb = smbase + (st) * QK_STAGE; \
        _Pragma("unroll") \
        for (int e = 0; e < 2; ++e) { \
            int idx = 2 * tid + e; \
            int r = idx >> 2, sg = idx & 3; \
            uint32_t doff = (uint32_t)r * QK_RS + sg * 16; \
            size_t goff = (size_t)r * D + (size_t)(c) * 32 + sg * 8; \
            cp16(sb + doff,               qh + goff); \
            cp16(sb + QK_TILE + doff,     ql + goff); \
            cp16(sb + 2 * QK_TILE + doff, kh + goff); \
            cp16(sb + 3 * QK_TILE + doff, kl + goff); \
        } } while (0)

    #define QK_COMPUTE(buf) do { \
        const char* Qh = sm + (buf) * QK_STAGE; \
        const char* Ql = Qh + QK_TILE; \
        const char* Kh = Qh + 2 * QK_TILE; \
        const char* Kl = Qh + 3 * QK_TILE; \
        _Pragma("unroll") \
        for (int s = 0; s < 2; ++s) { \
            const uint32_t so = (uint32_t)(s * 32 + t * 8); \
            uint2 ah[4][2], al[4][2]; \
            _Pragma("unroll") \
            for (int mt = 0; mt < 4; ++mt) { \
                uint32_t r0 = (uint32_t)(rm + mt * 16 + g) * QK_RS + so; \
                ah[mt][0] = *(const uint2*)(Qh + r0); \
                ah[mt][1] = *(const uint2*)(Qh + r0 + 8 * QK_RS); \
                al[mt][0] = *(const uint2*)(Ql + r0); \
                al[mt][1] = *(const uint2*)(Ql + r0 + 8 * QK_RS); \
            } \
            _Pragma("unroll") \
            for (int nt = 0; nt < 4; ++nt) { \
                uint32_t rb = (uint32_t)(rn + nt * 8 + g) * QK_RS + so; \
                uint2 bh = *(const uint2*)(Kh + rb); \
                uint2 bl = *(const uint2*)(Kl + rb); \
                _Pragma("unroll") \
                for (int mt = 0; mt < 4; ++mt) { \
                    mma_bf16(acc[mt][nt], ah[mt][0].x, ah[mt][1].x, ah[mt][0].y, ah[mt][1].y, bh.x, bh.y); \
                    mma_bf16(acc[mt][nt], ah[mt][0].x, ah[mt][1].x, ah[mt][0].y, ah[mt][1].y, bl.x, bl.y); \
                    mma_bf16(acc[mt][nt], al[mt][0].x, al[mt][1].x, al[mt][0].y, al[mt][1].y, bh.x, bh.y); \
                } \
            } \
        } } while (0)

    QK_LOAD(0, 0); CP_COMMIT();
    for (int c = 0; c < QK_NC; ++c) {
        CP_WAIT(0);
        __syncthreads();
        if (c + 1 < QK_NC) { QK_LOAD(c + 1, (c + 1) & 1); CP_COMMIT(); }
        QK_COMPUTE(c & 1);
    }

    // raw score writeback (masking happens in rowstats)
    #pragma unroll
    for (int mt = 0; mt < 4; ++mt) {
        int r0 = rm + mt * 16 + g;
        float* row0 = g_scores + ((size_t)b * L + ti + r0) * L + tj;
        float* row1 = row0 + (size_t)8 * L;
        #pragma unroll
        for (int nt = 0; nt < 4; ++nt) {
            int c0 = rn + nt * 8 + 2 * t;
            *(float2*)(row0 + c0) = make_float2(acc[mt][nt][0], acc[mt][nt][1]);
            *(float2*)(row1 + c0) = make_float2(acc[mt][nt][2], acc[mt][nt][3]);
        }
    }
}

// ---------------------------------------------------------------------------
// Kernel 2: masking + softmax stats + write final probabilities as fp16.
// ---------------------------------------------------------------------------
__global__ __launch_bounds__(256) void rowstats_kernel(const int* __restrict__ mask)
{
    const int row = blockIdx.x;            // b*L + i
    const int b = row >> 11;
    const int i = row & (L - 1);
    const float* s = g_scores + (size_t)row * L;
    const int* mb = mask + b * L;
    const int tid = threadIdx.x;
    const int base = tid * 8;
    const float mi = (float)mb[i];

    float v[8], m[8];
    float4 v0 = *(const float4*)(s + base);
    float4 v1 = *(const float4*)(s + base + 4);
    int4 m0 = *(const int4*)(mb + base);
    int4 m1 = *(const int4*)(mb + base + 4);
    v[0]=v0.x; v[1]=v0.y; v[2]=v0.z; v[3]=v0.w;
    v[4]=v1.x; v[5]=v1.y; v[6]=v1.z; v[7]=v1.w;
    m[0]=(float)m0.x*mi; m[1]=(float)m0.y*mi; m[2]=(float)m0.z*mi; m[3]=(float)m0.w*mi;
    m[4]=(float)m1.x*mi; m[5]=(float)m1.y*mi; m[6]=(float)m1.z*mi; m[7]=(float)m1.w*mi;

    #pragma unroll
    for (int e = 0; e < 8; e++) v[e] *= m[e];     // masked scores

    __shared__ float sredA[8], sredB[8];
    const unsigned full = 0xffffffffu;

    float lmax = v[0];
    #pragma unroll
    for (int e = 1; e < 8; e++) lmax = fmaxf(lmax, v[e]);
    #pragma unroll
    for (int o = 16; o > 0; o >>= 1) lmax = fmaxf(lmax, __shfl_xor_sync(full, lmax, o));
    if ((tid & 31) == 0) sredA[tid >> 5] = lmax;
    __syncthreads();
    float bmax = sredA[0];
    #pragma unroll
    for (int w = 1; w < 8; w++) bmax = fmaxf(bmax, sredA[w]);

    float p[8];
    float lsum = 0.0f;
    #pragma unroll
    for (int e = 0; e < 8; e++) { p[e] = __expf(v[e] - bmax) * m[e]; lsum += p[e]; }
    #pragma unroll
    for (int o = 16; o > 0; o >>= 1) lsum += __shfl_xor_sync(full, lsum, o);
    if ((tid & 31) == 0) sredB[tid >> 5] = lsum;
    __syncthreads();
    float bsum = 0.0f;
    #pragma unroll
    for (int w = 0; w < 8; w++) bsum += sredB[w];

    const float denom = bsum + ((bsum == 0.0f) ? 1.0f : 0.0f) + 1e-20f;
    const float scale = 1.0f / denom;

    uint32_t u[4];
    #pragma unroll
    for (int e = 0; e < 4; ++e) {
        __half2 hp = __floats2half2_rn(p[2*e] * scale, p[2*e+1] * scale);
        u[e] = *(uint32_t*)&hp;
    }
    *(uint4*)(g_probs + (size_t)row * L + base) = make_uint4(u[0], u[1], u[2], u[3]);
}

// ---------------------------------------------------------------------------
// Kernel 3: O = P V, fp16 mma.m16n8k16.  4-stage cp.async, 2 CTAs/SM.
// ---------------------------------------------------------------------------
#define PV_RS    80
#define PV_TILE  (128 * PV_RS)       // 10240
#define PV_STAGE (2 * PV_TILE)       // 20480
#define PV_NC    (L / 32)            // 64 stages

__global__ __launch_bounds__(256, 2) void pv_kernel(float* __restrict__ out)
{
    extern __shared__ char sm[];
    const uint32_t smbase = smem_u32(sm);
    const int tid = threadIdx.x, lane = tid & 31, wid = tid >> 5;
    const int g = lane >> 2, t = lane & 3;
    const int b = blockIdx.z, ti = blockIdx.y * 128, td = blockIdx.x * 128;

    const __half* pb  = g_probs + ((size_t)b * L + ti) * L;
    const __half* vtb = g_vt + ((size_t)b * D + td) * L;

    float acc[4][4][4];
    #pragma unroll
    for (int a = 0; a < 4; a++)
        #pragma unroll
        for (int bb = 0; bb < 4; bb++)
            #pragma unroll
            for (int cc = 0; cc < 4; cc++) acc[a][bb][cc] = 0.0f;

    const int rm = (wid >> 2) * 64, rn = (wid & 3) * 32;

    #define PV_LOAD(c, st) do { \
        uint32_t sb = smbase + (st) * PV_STAGE; \
        _Pragma("unroll") \
        for (int e = 0; e < 2; ++e) { \
            int idx = 2 * tid + e; \
            int r = idx >> 2, sg = idx & 3; \
            uint32_t doff = (uint32_t)r * PV_RS + sg * 16; \
            size_t goff = (size_t)r * L + (size_t)(c) * 32 + sg * 8; \
            cp16(sb + doff,           pb  + goff); \
            cp16(sb + PV_TILE + doff, vtb + goff); \
        } } while (0)

    #define PV_COMPUTE(buf) do { \
        const char* Pt = sm + (buf) * PV_STAGE; \
        const char* Vt = Pt + PV_TILE; \
        _Pragma("unroll") \
        for (int s = 0; s < 2; ++s) { \
            const uint32_t so = (uint32_t)(32 * s + 4 * t); \
            uint32_t a0[4], a1[4], a2[4], a3[4]; \
            _Pragma("unroll") \
            for (int mt = 0; mt < 4; ++mt) { \
                uint32_t r0 = (uint32_t)(rm + mt * 16 + g) * PV_RS + so; \
                a0[mt] = *(const uint32_t*)(Pt + r0); \
                a2[mt] = *(const uint32_t*)(Pt + r0 + 16); \
                a1[mt] = *(const uint32_t*)(Pt + r0 + 8 * PV_RS); \
                a3[mt] = *(const uint32_t*)(Pt + r0 + 8 * PV_RS + 16); \
            } \
            _Pragma("unroll") \
            for (int nt = 0; nt < 4; ++nt) { \
                uint32_t rb = (uint32_t)(rn + nt * 8 + g) * PV_RS + so; \
                uint32_t b0 = *(const uint32_t*)(Vt + rb); \
                uint32_t b1 = *(const uint32_t*)(Vt + rb + 16); \
                _Pragma("unroll") \
                for (int mt = 0; mt < 4; ++mt) \
                    mma_f16(acc[mt][nt], a0[mt], a1[mt], a2[mt], a3[mt], b0, b1); \
            } \
        } } while (0)

    PV_LOAD(0, 0); CP_COMMIT();
    PV_LOAD(1, 1); CP_COMMIT();
    for (int c = 0; c < PV_NC; ++c) {
        CP_WAIT(1);
        __syncthreads();
        if (c + 2 < PV_NC) { PV_LOAD(c + 2, (c + 2) & 3); }
        CP_COMMIT();
        PV_COMPUTE(c & 3);
    }

    #pragma unroll
    for (int mt = 0; mt < 4; ++mt) {
        int r0 = rm + mt * 16 + g;
        float* row0 = out + ((size_t)b * L + ti + r0) * D + td;
        float* row1 = row0 + (size_t)8 * D;
        #pragma unroll
        for (int nt = 0; nt < 4; ++nt) {
            int c0 = rn + nt * 8 + 2 * t;
            *(float2*)(row0 + c0) = make_float2(acc[mt][nt][0], acc[mt][nt][1]);
            *(float2*)(row1 + c0) = make_float2(acc[mt][nt][2], acc[mt][nt][3]);
        }
    }
}

// ---------------------------------------------------------------------------
extern "C" void kernel_launch(void* const* d_in, const int* in_sizes, int n_in,
                              void* d_out, int out_size)
{
    const float* q    = (const float*)d_in[0];
    const float* k    = (const float*)d_in[1];
    const float* v    = (const float*)d_in[2];
    const int*   mask = (const int*)d_in[3];
    float*       out  = (float*)d_out;

    cudaFuncSetAttribute(qk_kernel, cudaFuncAttributeMaxDynamicSharedMemorySize, 2 * QK_STAGE);
    cudaFuncSetAttribute(pv_kernel, cudaFuncAttributeMaxDynamicSharedMemorySize, 4 * PV_STAGE);

    prep_qk_kernel<<<dim3((B * L * D / 16) / 256, 2, 1), 256>>>(q, k);
    prep_v_kernel<<<dim3(L / 64, D / 32, B), 256>>>(v);

    dim3 g1(L / 128, L / 128, B);
    qk_kernel<<<g1, 256, 2 * QK_STAGE>>>();

    rowstats_kernel<<<B * L, 256>>>(mask);

    dim3 g3(D / 128, L / 128, B);
    pv_kernel<<<g3, 256, 4 * PV_STAGE>>>(out);
}

// round 7
// speedup vs baseline: 7.1703x; 2.5609x over previous
#include <cuda_runtime.h>
#include <cuda_bf16.h>
#include <cuda_fp16.h>
#include <math.h>
#include <stdint.h>

#define B 8
#define L 2048
#define D 1024

// scratch (compacted index space)
__device__ float         g_scores[(size_t)B * L * L];
__device__ __half        g_probs[(size_t)B * L * L];
__device__ __nv_bfloat16 g_qh[(size_t)B * L * D];
__device__ __nv_bfloat16 g_ql[(size_t)B * L * D];
__device__ __nv_bfloat16 g_kh[(size_t)B * L * D];
__device__ __nv_bfloat16 g_kl[(size_t)B * L * D];
__device__ __half        g_vt[(size_t)B * L * D];   // gathered V^T: [b][d][jj]
__device__ int           g_idx[B * L];              // valid row indices per batch
__device__ int           g_nv[B];                   // valid count per batch

// ---------------------------------------------------------------------------
// helpers
// ---------------------------------------------------------------------------
__device__ __forceinline__ uint32_t smem_u32(const void* p) {
    uint32_t a;
    asm("{ .reg .u64 t; cvta.to.shared.u64 t, %1; cvt.u32.u64 %0, t; }" : "=r"(a) : "l"(p));
    return a;
}
__device__ __forceinline__ void cp16(uint32_t dst, const void* src) {
    asm volatile("cp.async.cg.shared.global [%0], [%1], 16;" :: "r"(dst), "l"(src) : "memory");
}
#define CP_COMMIT() asm volatile("cp.async.commit_group;" ::: "memory")
#define CP_WAIT(n)  asm volatile("cp.async.wait_group %0;" :: "n"(n) : "memory")

__device__ __forceinline__ void mma_bf16(float c[4], uint32_t a0, uint32_t a1,
                                         uint32_t a2, uint32_t a3,
                                         uint32_t b0, uint32_t b1) {
    asm volatile(
        "mma.sync.aligned.m16n8k16.row.col.f32.bf16.bf16.f32 "
        "{%0,%1,%2,%3}, {%4,%5,%6,%7}, {%8,%9}, {%0,%1,%2,%3};"
        : "+f"(c[0]), "+f"(c[1]), "+f"(c[2]), "+f"(c[3])
        : "r"(a0), "r"(a1), "r"(a2), "r"(a3), "r"(b0), "r"(b1));
}
__device__ __forceinline__ void mma_f16(float c[4], uint32_t a0, uint32_t a1,
                                        uint32_t a2, uint32_t a3,
                                        uint32_t b0, uint32_t b1) {
    asm volatile(
        "mma.sync.aligned.m16n8k16.row.col.f32.f16.f16.f32 "
        "{%0,%1,%2,%3}, {%4,%5,%6,%7}, {%8,%9}, {%0,%1,%2,%3};"
        : "+f"(c[0]), "+f"(c[1]), "+f"(c[2]), "+f"(c[3])
        : "r"(a0), "r"(a1), "r"(a2), "r"(a3), "r"(b0), "r"(b1));
}

// ---------------------------------------------------------------------------
// Kernel 0a: per-batch compaction of valid indices (block-wide prefix sum)
// ---------------------------------------------------------------------------
__global__ __launch_bounds__(256) void compact_kernel(const int* __restrict__ mask)
{
    const int b = blockIdx.x;
    const int tid = threadIdx.x, lane = tid & 31, wid = tid >> 5;
    const int* mb = mask + b * L;
    __shared__ int wsum[8];

    int m[8];
    int4 a = *(const int4*)(mb + tid * 8);
    int4 c = *(const int4*)(mb + tid * 8 + 4);
    m[0]=a.x; m[1]=a.y; m[2]=a.z; m[3]=a.w;
    m[4]=c.x; m[5]=c.y; m[6]=c.z; m[7]=c.w;

    int tot = 0;
    #pragma unroll
    for (int e = 0; e < 8; e++) tot += m[e];

    int inc = tot;
    #pragma unroll
    for (int o = 1; o < 32; o <<= 1) {
        int v = __shfl_up_sync(0xffffffffu, inc, o);
        if (lane >= o) inc += v;
    }
    if (lane == 31) wsum[wid] = inc;
    __syncthreads();
    int woff = 0;
    #pragma unroll
    for (int w = 0; w < 8; w++) if (w < wid) woff += wsum[w];

    int pos = woff + inc - tot;        // exclusive prefix
    #pragma unroll
    for (int e = 0; e < 8; e++)
        if (m[e]) g_idx[b * L + pos++] = tid * 8 + e;

    if (tid == 255) g_nv[b] = woff + inc;
}

// ---------------------------------------------------------------------------
// Kernel 0b: zero-fill output rows with m_i == 0 (out is poisoned)
// ---------------------------------------------------------------------------
__global__ __launch_bounds__(256) void zerofill_kernel(
    const int* __restrict__ mask, float* __restrict__ out)
{
    const int row = blockIdx.x;
    const int b = row >> 11, i = row & (L - 1);
    if (mask[b * L + i]) return;
    float4 z = make_float4(0.f, 0.f, 0.f, 0.f);
    *(float4*)(out + ((size_t)b * L + i) * D + threadIdx.x * 4) = z;
}

// ---------------------------------------------------------------------------
// Prep 1: gather q,k valid rows -> bf16 hi/lo, k-pair-interleaved layout.
// ---------------------------------------------------------------------------
__global__ __launch_bounds__(256) void prep_qk_kernel(
    const float* __restrict__ q, const float* __restrict__ k)
{
    const float* src = blockIdx.y ? k : q;
    __nv_bfloat16* dh = blockIdx.y ? g_kh : g_qh;
    __nv_bfloat16* dl = blockIdx.y ? g_kl : g_ql;
    size_t gi = (size_t)blockIdx.x * 256 + threadIdx.x;   // 16-elem group id
    const int row = (int)(gi >> 6);                       // D/16 = 64 groups/row
    const int b = row >> 11, ii = row & (L - 1);
    if (ii >= g_nv[b]) return;
    const int gidx = g_idx[b * L + ii];
    const float* s = src + ((size_t)b * L + gidx) * D + (gi & 63) * 16;

    uint32_t h[8], l[8];
    #pragma unroll
    for (int qd = 0; qd < 4; ++qd) {
        float4 x = *(const float4*)(s + 4 * qd);
        __nv_bfloat162 h0 = __floats2bfloat162_rn(x.x, x.y);
        __nv_bfloat162 h1 = __floats2bfloat162_rn(x.z, x.w);
        float2 b0 = __bfloat1622float2(h0), b1 = __bfloat1622float2(h1);
        __nv_bfloat162 l0 = __floats2bfloat162_rn(x.x - b0.x, x.y - b0.y);
        __nv_bfloat162 l1 = __floats2bfloat162_rn(x.z - b1.x, x.w - b1.y);
        h[2*qd] = *(uint32_t*)&h0; h[2*qd+1] = *(uint32_t*)&h1;
        l[2*qd] = *(uint32_t*)&l0; l[2*qd+1] = *(uint32_t*)&l1;
    }
    *(uint4*)(dh + gi * 16)     = make_uint4(h[0], h[4], h[1], h[5]);
    *(uint4*)(dh + gi * 16 + 8) = make_uint4(h[2], h[6], h[3], h[7]);
    *(uint4*)(dl + gi * 16)     = make_uint4(l[0], l[4], l[1], l[5]);
    *(uint4*)(dl + gi * 16 + 8) = make_uint4(l[2], l[6], l[3], l[7]);
}

// ---------------------------------------------------------------------------
// Prep 2: gather V valid rows, f32 [b][j][d] -> fp16 transposed [b][d][jj].
// Columns jj >= nv written as zeros.
// ---------------------------------------------------------------------------
__global__ __launch_bounds__(256) void prep_v_kernel(const float* __restrict__ v)
{
    __shared__ __half t[32][72];
    const int b = blockIdx.z, d0 = blockIdx.y * 32, j0 = blockIdx.x * 64;
    const int nv = g_nv[b];
    const int tid = threadIdx.x;
    const int dd = tid & 31, jw = tid >> 5;
    #pragma unroll
    for (int it = 0; it < 8; ++it) {
        int jj = jw + it * 8;
        int jg = j0 + jj;
        float x = 0.0f;
        if (jg < nv) x = v[((size_t)b * L + g_idx[b * L + jg]) * D + d0 + dd];
        t[dd][jj] = __float2half_rn(x);
    }
    __syncthreads();
    const int row = tid >> 3, c8 = (tid & 7) * 8;
    uint32_t u[4];
    #pragma unroll
    for (int e = 0; e < 4; ++e) {
        __half2 hp; hp.x = t[row][c8 + 2*e]; hp.y = t[row][c8 + 2*e + 1];
        u[e] = *(uint32_t*)&hp;
    }
    *(uint4*)(g_vt + ((size_t)b * D + d0 + row) * L + j0 + c8) =
        make_uint4(u[0], u[1], u[2], u[3]);
}

// ---------------------------------------------------------------------------
// Kernel 1: compacted S = Qc Kc^T (raw), bf16 3-term split. Tiles beyond
// ceil(nv/128) exit. k-dim = D (full).
// ---------------------------------------------------------------------------
#define QK_RS    96
#define QK_TILE  (128 * QK_RS)
#define QK_STAGE (4 * QK_TILE)       // 49152
#define QK_NC    (D / 32)

__global__ __launch_bounds__(256, 2) void qk_kernel()
{
    const int b = blockIdx.z;
    const int nv = g_nv[b];
    const int ntile = (nv + 127) >> 7;
    if ((int)blockIdx.x >= ntile || (int)blockIdx.y >= ntile) return;

    extern __shared__ char sm[];
    const uint32_t smbase = smem_u32(sm);
    const int tid = threadIdx.x, lane = tid & 31, wid = tid >> 5;
    const int g = lane >> 2, t = lane & 3;
    const int ti = blockIdx.y * 128, tj = blockIdx.x * 128;

    const __nv_bfloat16* qh = g_qh + ((size_t)b * L + ti) * D;
    const __nv_bfloat16* ql = g_ql + ((size_t)b * L + ti) * D;
    const __nv_bfloat16* kh = g_kh + ((size_t)b * L + tj) * D;
    const __nv_bfloat16* kl = g_kl + ((size_t)b * L + tj) * D;

    float acc[4][4][4];
    #pragma unroll
    for (int a = 0; a < 4; a++)
        #pragma unroll
        for (int bb = 0; bb < 4; bb++)
            #pragma unroll
            for (int cc = 0; cc < 4; cc++) acc[a][bb][cc] = 0.0f;

    const int rm = (wid >> 2) * 64, rn = (wid & 3) * 32;

    #define QK_LOAD(c, st) do { \
        uint32_t sb = smbase + (st) * QK_STAGE; \
        _Pragma("unroll") \
        for (int e = 0; e < 2; ++e) { \
            int idx = 2 * tid + e; \
            int r = idx >> 2, sg = idx & 3; \
            uint32_t doff = (uint32_t)r * QK_RS + sg * 16; \
            size_t goff = (size_t)r * D + (size_t)(c) * 32 + sg * 8; \
            cp16(sb + doff,               qh + goff); \
            cp16(sb + QK_TILE + doff,     ql + goff); \
            cp16(sb + 2 * QK_TILE + doff, kh + goff); \
            cp16(sb + 3 * QK_TILE + doff, kl + goff); \
        } } while (0)

    #define QK_COMPUTE(buf) do { \
        const char* Qh = sm + (buf) * QK_STAGE; \
        const char* Ql = Qh + QK_TILE; \
        const char* Kh = Qh + 2 * QK_TILE; \
        const char* Kl = Qh + 3 * QK_TILE; \
        _Pragma("unroll") \
        for (int s = 0; s < 2; ++s) { \
            const uint32_t so = (uint32_t)(s * 32 + t * 8); \
            uint2 ah[4][2], al[4][2]; \
            _Pragma("unroll") \
            for (int mt = 0; mt < 4; ++mt) { \
                uint32_t r0 = (uint32_t)(rm + mt * 16 + g) * QK_RS + so; \
                ah[mt][0] = *(const uint2*)(Qh + r0); \
                ah[mt][1] = *(const uint2*)(Qh + r0 + 8 * QK_RS); \
                al[mt][0] = *(const uint2*)(Ql + r0); \
                al[mt][1] = *(const uint2*)(Ql + r0 + 8 * QK_RS); \
            } \
            _Pragma("unroll") \
            for (int nt = 0; nt < 4; ++nt) { \
                uint32_t rb = (uint32_t)(rn + nt * 8 + g) * QK_RS + so; \
                uint2 bh = *(const uint2*)(Kh + rb); \
                uint2 bl = *(const uint2*)(Kl + rb); \
                _Pragma("unroll") \
                for (int mt = 0; mt < 4; ++mt) { \
                    mma_bf16(acc[mt][nt], ah[mt][0].x, ah[mt][1].x, ah[mt][0].y, ah[mt][1].y, bh.x, bh.y); \
                    mma_bf16(acc[mt][nt], ah[mt][0].x, ah[mt][1].x, ah[mt][0].y, ah[mt][1].y, bl.x, bl.y); \
                    mma_bf16(acc[mt][nt], al[mt][0].x, al[mt][1].x, al[mt][0].y, al[mt][1].y, bh.x, bh.y); \
                } \
            } \
        } } while (0)

    QK_LOAD(0, 0); CP_COMMIT();
    for (int c = 0; c < QK_NC; ++c) {
        CP_WAIT(0);
        __syncthreads();
        if (c + 1 < QK_NC) { QK_LOAD(c + 1, (c + 1) & 1); CP_COMMIT(); }
        QK_COMPUTE(c & 1);
    }

    #pragma unroll
    for (int mt = 0; mt < 4; ++mt) {
        int r0 = rm + mt * 16 + g;
        float* row0 = g_scores + ((size_t)b * L + ti + r0) * L + tj;
        float* row1 = row0 + (size_t)8 * L;
        #pragma unroll
        for (int nt = 0; nt < 4; ++nt) {
            int c0 = rn + nt * 8 + 2 * t;
            *(float2*)(row0 + c0) = make_float2(acc[mt][nt][0], acc[mt][nt][1]);
            *(float2*)(row1 + c0) = make_float2(acc[mt][nt][2], acc[mt][nt][3]);
        }
    }
}

// ---------------------------------------------------------------------------
// Kernel 2: softmax over compacted row (length nv). All compact m==1, so
// p = exp(s - max)/denom with max clamped at 0 iff nv<L. Pads probs with
// zeros up to ceil(nv/32)*32.
// ---------------------------------------------------------------------------
__global__ __launch_bounds__(256) void rowstats_kernel()
{
    const int row = blockIdx.x;            // b*L + ii (compact)
    const int b = row >> 11;
    const int ii = row & (L - 1);
    const int nv = g_nv[b];
    if (ii >= nv) return;
    const float* s = g_scores + (size_t)row * L;
    const int tid = threadIdx.x;
    const int base = tid * 8;

    float vv[8];
    if (base + 8 <= nv) {
        float4 v0 = *(const float4*)(s + base);
        float4 v1 = *(const float4*)(s + base + 4);
        vv[0]=v0.x; vv[1]=v0.y; vv[2]=v0.z; vv[3]=v0.w;
        vv[4]=v1.x; vv[5]=v1.y; vv[6]=v1.z; vv[7]=v1.w;
    } else {
        #pragma unroll
        for (int e = 0; e < 8; e++)
            vv[e] = (base + e < nv) ? s[base + e] : -INFINITY;
    }

    __shared__ float sredA[8], sredB[8];
    const unsigned full = 0xffffffffu;

    float lmax = vv[0];
    #pragma unroll
    for (int e = 1; e < 8; e++) lmax = fmaxf(lmax, vv[e]);
    #pragma unroll
    for (int o = 16; o > 0; o >>= 1) lmax = fmaxf(lmax, __shfl_xor_sync(full, lmax, o));
    if ((tid & 31) == 0) sredA[tid >> 5] = lmax;
    __syncthreads();
    float bmax = sredA[0];
    #pragma unroll
    for (int w = 1; w < 8; w++) bmax = fmaxf(bmax, sredA[w]);
    if (nv < L) bmax = fmaxf(bmax, 0.0f);   // literal zeros at masked cols

    float p[8];
    float lsum = 0.0f;
    #pragma unroll
    for (int e = 0; e < 8; e++) { p[e] = __expf(vv[e] - bmax); lsum += p[e]; }
    // invalid lanes: exp(-inf)=0
    #pragma unroll
    for (int o = 16; o > 0; o >>= 1) lsum += __shfl_xor_sync(full, lsum, o);
    if ((tid & 31) == 0) sredB[tid >> 5] = lsum;
    __syncthreads();
    float bsum = 0.0f;
    #pragma unroll
    for (int w = 0; w < 8; w++) bsum += sredB[w];

    const float denom = bsum + ((bsum == 0.0f) ? 1.0f : 0.0f) + 1e-20f;
    const float scale = 1.0f / denom;

    const int ncpad = ((nv + 31) >> 5) << 5;
    if (base < ncpad) {
        uint32_t u[4];
        #pragma unroll
        for (int e = 0; e < 4; ++e) {
            __half2 hp = __floats2half2_rn(p[2*e] * scale, p[2*e+1] * scale);
            u[e] = *(uint32_t*)&hp;
        }
        *(uint4*)(g_probs + (size_t)row * L + base) = make_uint4(u[0], u[1], u[2], u[3]);
    }
}

// ---------------------------------------------------------------------------
// Kernel 3: Oc = Pc Vc (fp16 mma), then scatter rows to out via g_idx.
// ---------------------------------------------------------------------------
#define PV_RS    80
#define PV_TILE  (128 * PV_RS)
#define PV_STAGE (2 * PV_TILE)       // 20480

__global__ __launch_bounds__(256, 2) void pv_kernel(float* __restrict__ out)
{
    const int b = blockIdx.z;
    const int nv = g_nv[b];
    const int ntile = (nv + 127) >> 7;
    if ((int)blockIdx.y >= ntile) return;
    const int NC = (nv + 31) >> 5;

    extern __shared__ char sm[];
    const uint32_t smbase = smem_u32(sm);
    const int tid = threadIdx.x, lane = tid & 31, wid = tid >> 5;
    const int g = lane >> 2, t = lane & 3;
    const int ti = blockIdx.y * 128, td = blockIdx.x * 128;

    const __half* pb  = g_probs + ((size_t)b * L + ti) * L;
    const __half* vtb = g_vt + ((size_t)b * D + td) * L;

    float acc[4][4][4];
    #pragma unroll
    for (int a = 0; a < 4; a++)
        #pragma unroll
        for (int bb = 0; bb < 4; bb++)
            #pragma unroll
            for (int cc = 0; cc < 4; cc++) acc[a][bb][cc] = 0.0f;

    const int rm = (wid >> 2) * 64, rn = (wid & 3) * 32;

    #define PV_LOAD(c, st) do { \
        uint32_t sb = smbase + (st) * PV_STAGE; \
        _Pragma("unroll") \
        for (int e = 0; e < 2; ++e) { \
            int idx = 2 * tid + e; \
            int r = idx >> 2, sg = idx & 3; \
            uint32_t doff = (uint32_t)r * PV_RS + sg * 16; \
            size_t goff = (size_t)r * L + (size_t)(c) * 32 + sg * 8; \
            cp16(sb + doff,           pb  + goff); \
            cp16(sb + PV_TILE + doff, vtb + goff); \
        } } while (0)

    #define PV_COMPUTE(buf) do { \
        const char* Pt = sm + (buf) * PV_STAGE; \
        const char* Vt = Pt + PV_TILE; \
        _Pragma("unroll") \
        for (int s = 0; s < 2; ++s) { \
            const uint32_t so = (uint32_t)(32 * s + 4 * t); \
            uint32_t a0[4], a1[4], a2[4], a3[4]; \
            _Pragma("unroll") \
            for (int mt = 0; mt < 4; ++mt) { \
                uint32_t r0 = (uint32_t)(rm + mt * 16 + g) * PV_RS + so; \
                a0[mt] = *(const uint32_t*)(Pt + r0); \
                a2[mt] = *(const uint32_t*)(Pt + r0 + 16); \
                a1[mt] = *(const uint32_t*)(Pt + r0 + 8 * PV_RS); \
                a3[mt] = *(const uint32_t*)(Pt + r0 + 8 * PV_RS + 16); \
            } \
            _Pragma("unroll") \
            for (int nt = 0; nt < 4; ++nt) { \
                uint32_t rb = (uint32_t)(rn + nt * 8 + g) * PV_RS + so; \
                uint32_t b0 = *(const uint32_t*)(Vt + rb); \
                uint32_t b1 = *(const uint32_t*)(Vt + rb + 16); \
                _Pragma("unroll") \
                for (int mt = 0; mt < 4; ++mt) \
                    mma_f16(acc[mt][nt], a0[mt], a1[mt], a2[mt], a3[mt], b0, b1); \
            } \
        } } while (0)

    if (NC > 0) PV_LOAD(0, 0);
    CP_COMMIT();
    if (NC > 1) PV_LOAD(1, 1);
    CP_COMMIT();
    for (int c = 0; c < NC; ++c) {
        CP_WAIT(1);
        __syncthreads();
        if (c + 2 < NC) { PV_LOAD(c + 2, (c + 2) & 3); }
        CP_COMMIT();
        PV_COMPUTE(c & 3);
    }

    const int* idxb = g_idx + b * L;
    #pragma unroll
    for (int mt = 0; mt < 4; ++mt) {
        int r0 = rm + mt * 16 + g;
        int i0 = ti + r0, i1 = i0 + 8;
        #pragma unroll
        for (int half = 0; half < 2; ++half) {
            int irow = half ? i1 : i0;
            if (irow < nv) {
                float* orow = out + ((size_t)b * L + idxb[irow]) * D + td;
                #pragma unroll
                for (int nt = 0; nt < 4; ++nt) {
                    int c0 = rn + nt * 8 + 2 * t;
                    *(float2*)(orow + c0) = half
                        ? make_float2(acc[mt][nt][2], acc[mt][nt][3])
                        : make_float2(acc[mt][nt][0], acc[mt][nt][1]);
                }
            }
        }
    }
}

// ---------------------------------------------------------------------------
extern "C" void kernel_launch(void* const* d_in, const int* in_sizes, int n_in,
                              void* d_out, int out_size)
{
    const float* q    = (const float*)d_in[0];
    const float* k    = (const float*)d_in[1];
    const float* v    = (const float*)d_in[2];
    const int*   mask = (const int*)d_in[3];
    float*       out  = (float*)d_out;

    cudaFuncSetAttribute(qk_kernel, cudaFuncAttributeMaxDynamicSharedMemorySize, 2 * QK_STAGE);
    cudaFuncSetAttribute(pv_kernel, cudaFuncAttributeMaxDynamicSharedMemorySize, 4 * PV_STAGE);

    compact_kernel<<<B, 256>>>(mask);
    zerofill_kernel<<<B * L, 256>>>(mask, out);
    prep_qk_kernel<<<dim3((B * L * D / 16) / 256, 2, 1), 256>>>(q, k);
    prep_v_kernel<<<dim3(L / 64, D / 32, B), 256>>>(v);

    dim3 g1(L / 128, L / 128, B);
    qk_kernel<<<g1, 256, 2 * QK_STAGE>>>();

    rowstats_kernel<<<B * L, 256>>>();

    dim3 g3(D / 128, L / 128, B);
    pv_kernel<<<g3, 256, 4 * PV_STAGE>>>(out);
}

// round 8
// speedup vs baseline: 7.3756x; 1.0286x over previous
#include <cuda_runtime.h>
#include <cuda_bf16.h>
#include <cuda_fp16.h>
#include <math.h>
#include <stdint.h>

#define B 8
#define L 2048
#define D 1024

// scratch (compacted index space)
__device__ float         g_scores[(size_t)B * L * L];
__device__ __half        g_probs[(size_t)B * L * L];
__device__ __nv_bfloat16 g_qh[(size_t)B * L * D];
__device__ __nv_bfloat16 g_ql[(size_t)B * L * D];
__device__ __nv_bfloat16 g_kh[(size_t)B * L * D];
__device__ __nv_bfloat16 g_kl[(size_t)B * L * D];
__device__ __half        g_vt[(size_t)B * L * D];   // gathered V^T: [b][d][jj]
__device__ int           g_idx[B * L];
__device__ int           g_nv[B];

// ---------------------------------------------------------------------------
__device__ __forceinline__ uint32_t smem_u32(const void* p) {
    uint32_t a;
    asm("{ .reg .u64 t; cvta.to.shared.u64 t, %1; cvt.u32.u64 %0, t; }" : "=r"(a) : "l"(p));
    return a;
}
__device__ __forceinline__ void cp16(uint32_t dst, const void* src) {
    asm volatile("cp.async.cg.shared.global [%0], [%1], 16;" :: "r"(dst), "l"(src) : "memory");
}
#define CP_COMMIT() asm volatile("cp.async.commit_group;" ::: "memory")
#define CP_WAIT(n)  asm volatile("cp.async.wait_group %0;" :: "n"(n) : "memory")

__device__ __forceinline__ void mma_bf16(float c[4], uint32_t a0, uint32_t a1,
                                         uint32_t a2, uint32_t a3,
                                         uint32_t b0, uint32_t b1) {
    asm volatile(
        "mma.sync.aligned.m16n8k16.row.col.f32.bf16.bf16.f32 "
        "{%0,%1,%2,%3}, {%4,%5,%6,%7}, {%8,%9}, {%0,%1,%2,%3};"
        : "+f"(c[0]), "+f"(c[1]), "+f"(c[2]), "+f"(c[3])
        : "r"(a0), "r"(a1), "r"(a2), "r"(a3), "r"(b0), "r"(b1));
}
__device__ __forceinline__ void mma_f16(float c[4], uint32_t a0, uint32_t a1,
                                        uint32_t a2, uint32_t a3,
                                        uint32_t b0, uint32_t b1) {
    asm volatile(
        "mma.sync.aligned.m16n8k16.row.col.f32.f16.f16.f32 "
        "{%0,%1,%2,%3}, {%4,%5,%6,%7}, {%8,%9}, {%0,%1,%2,%3};"
        : "+f"(c[0]), "+f"(c[1]), "+f"(c[2]), "+f"(c[3])
        : "r"(a0), "r"(a1), "r"(a2), "r"(a3), "r"(b0), "r"(b1));
}

// ---------------------------------------------------------------------------
// Kernel 0a: per-batch compaction of valid indices
// ---------------------------------------------------------------------------
__global__ __launch_bounds__(256) void compact_kernel(const int* __restrict__ mask)
{
    const int b = blockIdx.x;
    const int tid = threadIdx.x, lane = tid & 31, wid = tid >> 5;
    const int* mb = mask + b * L;
    __shared__ int wsum[8];

    int m[8];
    int4 a = *(const int4*)(mb + tid * 8);
    int4 c = *(const int4*)(mb + tid * 8 + 4);
    m[0]=a.x; m[1]=a.y; m[2]=a.z; m[3]=a.w;
    m[4]=c.x; m[5]=c.y; m[6]=c.z; m[7]=c.w;

    int tot = 0;
    #pragma unroll
    for (int e = 0; e < 8; e++) tot += m[e];

    int inc = tot;
    #pragma unroll
    for (int o = 1; o < 32; o <<= 1) {
        int v = __shfl_up_sync(0xffffffffu, inc, o);
        if (lane >= o) inc += v;
    }
    if (lane == 31) wsum[wid] = inc;
    __syncthreads();
    int woff = 0;
    #pragma unroll
    for (int w = 0; w < 8; w++) if (w < wid) woff += wsum[w];

    int pos = woff + inc - tot;
    #pragma unroll
    for (int e = 0; e < 8; e++)
        if (m[e]) g_idx[b * L + pos++] = tid * 8 + e;

    if (tid == 255) g_nv[b] = woff + inc;
}

// ---------------------------------------------------------------------------
// Kernel 0b: zero-fill output rows with m_i == 0
// ---------------------------------------------------------------------------
__global__ __launch_bounds__(256) void zerofill_kernel(
    const int* __restrict__ mask, float* __restrict__ out)
{
    const int row = blockIdx.x;
    const int b = row >> 11, i = row & (L - 1);
    if (mask[b * L + i]) return;
    float4 z = make_float4(0.f, 0.f, 0.f, 0.f);
    *(float4*)(out + ((size_t)b * L + i) * D + threadIdx.x * 4) = z;
}

// ---------------------------------------------------------------------------
// Prep 1: gather q,k valid rows -> bf16 hi/lo, k-pair-interleaved layout.
// ---------------------------------------------------------------------------
__global__ __launch_bounds__(256) void prep_qk_kernel(
    const float* __restrict__ q, const float* __restrict__ k)
{
    const float* src = blockIdx.y ? k : q;
    __nv_bfloat16* dh = blockIdx.y ? g_kh : g_qh;
    __nv_bfloat16* dl = blockIdx.y ? g_kl : g_ql;
    size_t gi = (size_t)blockIdx.x * 256 + threadIdx.x;
    const int row = (int)(gi >> 6);
    const int b = row >> 11, ii = row & (L - 1);
    if (ii >= g_nv[b]) return;
    const int gidx = g_idx[b * L + ii];
    const float* s = src + ((size_t)b * L + gidx) * D + (gi & 63) * 16;

    uint32_t h[8], l[8];
    #pragma unroll
    for (int qd = 0; qd < 4; ++qd) {
        float4 x = *(const float4*)(s + 4 * qd);
        __nv_bfloat162 h0 = __floats2bfloat162_rn(x.x, x.y);
        __nv_bfloat162 h1 = __floats2bfloat162_rn(x.z, x.w);
        float2 b0 = __bfloat1622float2(h0), b1 = __bfloat1622float2(h1);
        __nv_bfloat162 l0 = __floats2bfloat162_rn(x.x - b0.x, x.y - b0.y);
        __nv_bfloat162 l1 = __floats2bfloat162_rn(x.z - b1.x, x.w - b1.y);
        h[2*qd] = *(uint32_t*)&h0; h[2*qd+1] = *(uint32_t*)&h1;
        l[2*qd] = *(uint32_t*)&l0; l[2*qd+1] = *(uint32_t*)&l1;
    }
    *(uint4*)(dh + gi * 16)     = make_uint4(h[0], h[4], h[1], h[5]);
    *(uint4*)(dh + gi * 16 + 8) = make_uint4(h[2], h[6], h[3], h[7]);
    *(uint4*)(dl + gi * 16)     = make_uint4(l[0], l[4], l[1], l[5]);
    *(uint4*)(dl + gi * 16 + 8) = make_uint4(l[2], l[6], l[3], l[7]);
}

// ---------------------------------------------------------------------------
// Prep 2: gather V valid rows, f32 [b][j][d] -> fp16 transposed [b][d][jj].
// ---------------------------------------------------------------------------
__global__ __launch_bounds__(256) void prep_v_kernel(const float* __restrict__ v)
{
    __shared__ __half t[32][72];
    const int b = blockIdx.z, d0 = blockIdx.y * 32, j0 = blockIdx.x * 64;
    const int nv = g_nv[b];
    const int tid = threadIdx.x;
    const int dd = tid & 31, jw = tid >> 5;
    #pragma unroll
    for (int it = 0; it < 8; ++it) {
        int jj = jw + it * 8;
        int jg = j0 + jj;
        float x = 0.0f;
        if (jg < nv) x = v[((size_t)b * L + g_idx[b * L + jg]) * D + d0 + dd];
        t[dd][jj] = __float2half_rn(x);
    }
    __syncthreads();
    const int row = tid >> 3, c8 = (tid & 7) * 8;
    uint32_t u[4];
    #pragma unroll
    for (int e = 0; e < 4; ++e) {
        __half2 hp; hp.x = t[row][c8 + 2*e]; hp.y = t[row][c8 + 2*e + 1];
        u[e] = *(uint32_t*)&hp;
    }
    *(uint4*)(g_vt + ((size_t)b * D + d0 + row) * L + j0 + c8) =
        make_uint4(u[0], u[1], u[2], u[3]);
}

// ---------------------------------------------------------------------------
// Kernel 1: compacted S = Qc Kc^T, bf16 3-term split.
// Split-term loop hoisted: same-accumulator MMA distance = 4 (hides HMMA lat).
// ---------------------------------------------------------------------------
#define QK_RS    96
#define QK_TILE  (128 * QK_RS)
#define QK_STAGE (4 * QK_TILE)       // 49152
#define QK_NC    (D / 32)

__global__ __launch_bounds__(256, 2) void qk_kernel()
{
    const int b = blockIdx.z;
    const int nv = g_nv[b];
    const int ntile = (nv + 127) >> 7;
    if ((int)blockIdx.x >= ntile || (int)blockIdx.y >= ntile) return;

    extern __shared__ char sm[];
    const uint32_t smbase = smem_u32(sm);
    const int tid = threadIdx.x, lane = tid & 31, wid = tid >> 5;
    const int g = lane >> 2, t = lane & 3;
    const int ti = blockIdx.y * 128, tj = blockIdx.x * 128;

    const __nv_bfloat16* qh = g_qh + ((size_t)b * L + ti) * D;
    const __nv_bfloat16* ql = g_ql + ((size_t)b * L + ti) * D;
    const __nv_bfloat16* kh = g_kh + ((size_t)b * L + tj) * D;
    const __nv_bfloat16* kl = g_kl + ((size_t)b * L + tj) * D;

    float acc[4][4][4];
    #pragma unroll
    for (int a = 0; a < 4; a++)
        #pragma unroll
        for (int bb = 0; bb < 4; bb++)
            #pragma unroll
            for (int cc = 0; cc < 4; cc++) acc[a][bb][cc] = 0.0f;

    const int rm = (wid >> 2) * 64, rn = (wid & 3) * 32;

    #define QK_LOAD(c, st) do { \
        uint32_t sb = smbase + (st) * QK_STAGE; \
        _Pragma("unroll") \
        for (int e = 0; e < 2; ++e) { \
            int idx = 2 * tid + e; \
            int r = idx >> 2, sg = idx & 3; \
            uint32_t doff = (uint32_t)r * QK_RS + sg * 16; \
            size_t goff = (size_t)r * D + (size_t)(c) * 32 + sg * 8; \
            cp16(sb + doff,               qh + goff); \
            cp16(sb + QK_TILE + doff,     ql + goff); \
            cp16(sb + 2 * QK_TILE + doff, kh + goff); \
            cp16(sb + 3 * QK_TILE + doff, kl + goff); \
        } } while (0)

    // per nt: 3 term-passes, each a 4-long mt sweep -> same-acc distance 4
    #define QK_COMPUTE(buf) do { \
        const char* Qh = sm + (buf) * QK_STAGE; \
        const char* Ql = Qh + QK_TILE; \
        const char* Kh = Qh + 2 * QK_TILE; \
        const char* Kl = Qh + 3 * QK_TILE; \
        _Pragma("unroll") \
        for (int s = 0; s < 2; ++s) { \
            const uint32_t so = (uint32_t)(s * 32 + t * 8); \
            uint2 ah[4][2], al[4][2]; \
            _Pragma("unroll") \
            for (int mt = 0; mt < 4; ++mt) { \
                uint32_t r0 = (uint32_t)(rm + mt * 16 + g) * QK_RS + so; \
                ah[mt][0] = *(const uint2*)(Qh + r0); \
                ah[mt][1] = *(const uint2*)(Qh + r0 + 8 * QK_RS); \
                al[mt][0] = *(const uint2*)(Ql + r0); \
                al[mt][1] = *(const uint2*)(Ql + r0 + 8 * QK_RS); \
            } \
            _Pragma("unroll") \
            for (int nt = 0; nt < 4; ++nt) { \
                uint32_t rb = (uint32_t)(rn + nt * 8 + g) * QK_RS + so; \
                uint2 bh = *(const uint2*)(Kh + rb); \
                uint2 bl = *(const uint2*)(Kl + rb); \
                _Pragma("unroll") \
                for (int mt = 0; mt < 4; ++mt) \
                    mma_bf16(acc[mt][nt], ah[mt][0].x, ah[mt][1].x, ah[mt][0].y, ah[mt][1].y, bh.x, bh.y); \
                _Pragma("unroll") \
                for (int mt = 0; mt < 4; ++mt) \
                    mma_bf16(acc[mt][nt], ah[mt][0].x, ah[mt][1].x, ah[mt][0].y, ah[mt][1].y, bl.x, bl.y); \
                _Pragma("unroll") \
                for (int mt = 0; mt < 4; ++mt) \
                    mma_bf16(acc[mt][nt], al[mt][0].x, al[mt][1].x, al[mt][0].y, al[mt][1].y, bh.x, bh.y); \
            } \
        } } while (0)

    QK_LOAD(0, 0); CP_COMMIT();
    for (int c = 0; c < QK_NC; ++c) {
        CP_WAIT(0);
        __syncthreads();
        if (c + 1 < QK_NC) { QK_LOAD(c + 1, (c + 1) & 1); CP_COMMIT(); }
        QK_COMPUTE(c & 1);
    }

    #pragma unroll
    for (int mt = 0; mt < 4; ++mt) {
        int r0 = rm + mt * 16 + g;
        float* row0 = g_scores + ((size_t)b * L + ti + r0) * L + tj;
        float* row1 = row0 + (size_t)8 * L;
        #pragma unroll
        for (int nt = 0; nt < 4; ++nt) {
            int c0 = rn + nt * 8 + 2 * t;
            *(float2*)(row0 + c0) = make_float2(acc[mt][nt][0], acc[mt][nt][1]);
            *(float2*)(row1 + c0) = make_float2(acc[mt][nt][2], acc[mt][nt][3]);
        }
    }
}

// ---------------------------------------------------------------------------
// Kernel 2: softmax over compacted row (length nv).
// ---------------------------------------------------------------------------
__global__ __launch_bounds__(256) void rowstats_kernel()
{
    const int row = blockIdx.x;
    const int b = row >> 11;
    const int ii = row & (L - 1);
    const int nv = g_nv[b];
    if (ii >= nv) return;
    const float* s = g_scores + (size_t)row * L;
    const int tid = threadIdx.x;
    const int base = tid * 8;

    float vv[8];
    if (base + 8 <= nv) {
        float4 v0 = *(const float4*)(s + base);
        float4 v1 = *(const float4*)(s + base + 4);
        vv[0]=v0.x; vv[1]=v0.y; vv[2]=v0.z; vv[3]=v0.w;
        vv[4]=v1.x; vv[5]=v1.y; vv[6]=v1.z; vv[7]=v1.w;
    } else {
        #pragma unroll
        for (int e = 0; e < 8; e++)
            vv[e] = (base + e < nv) ? s[base + e] : -INFINITY;
    }

    __shared__ float sredA[8], sredB[8];
    const unsigned full = 0xffffffffu;

    float lmax = vv[0];
    #pragma unroll
    for (int e = 1; e < 8; e++) lmax = fmaxf(lmax, vv[e]);
    #pragma unroll
    for (int o = 16; o > 0; o >>= 1) lmax = fmaxf(lmax, __shfl_xor_sync(full, lmax, o));
    if ((tid & 31) == 0) sredA[tid >> 5] = lmax;
    __syncthreads();
    float bmax = sredA[0];
    #pragma unroll
    for (int w = 1; w < 8; w++) bmax = fmaxf(bmax, sredA[w]);
    if (nv < L) bmax = fmaxf(bmax, 0.0f);

    float p[8];
    float lsum = 0.0f;
    #pragma unroll
    for (int e = 0; e < 8; e++) { p[e] = __expf(vv[e] - bmax); lsum += p[e]; }
    #pragma unroll
    for (int o = 16; o > 0; o >>= 1) lsum += __shfl_xor_sync(full, lsum, o);
    if ((tid & 31) == 0) sredB[tid >> 5] = lsum;
    __syncthreads();
    float bsum = 0.0f;
    #pragma unroll
    for (int w = 0; w < 8; w++) bsum += sredB[w];

    const float denom = bsum + ((bsum == 0.0f) ? 1.0f : 0.0f) + 1e-20f;
    const float scale = 1.0f / denom;

    const int ncpad = ((nv + 63) >> 6) << 6;   // pad to BK=64 multiple
    if (base < ncpad) {
        uint32_t u[4];
        #pragma unroll
        for (int e = 0; e < 4; ++e) {
            __half2 hp = __floats2half2_rn(p[2*e] * scale, p[2*e+1] * scale);
            u[e] = *(uint32_t*)&hp;
        }
        *(uint4*)(g_probs + (size_t)row * L + base) = make_uint4(u[0], u[1], u[2], u[3]);
    }
}

// ---------------------------------------------------------------------------
// Kernel 3: Oc = Pc Vc (fp16 mma), BK=64, 2-stage, scatter rows via g_idx.
// RS=144: frag banks (4g+t) mod 32 all distinct -> conflict-free lds.32.
// ---------------------------------------------------------------------------
#define PV_RS    144
#define PV_TILE  (128 * PV_RS)       // 18432
#define PV_STAGE (2 * PV_TILE)       // 36864

__global__ __launch_bounds__(256, 2) void pv_kernel(float* __restrict__ out)
{
    const int b = blockIdx.z;
    const int nv = g_nv[b];
    const int ntile = (nv + 127) >> 7;
    if ((int)blockIdx.y >= ntile) return;
    const int NC = (nv + 63) >> 6;

    extern __shared__ char sm[];
    const uint32_t smbase = smem_u32(sm);
    const int tid = threadIdx.x, lane = tid & 31, wid = tid >> 5;
    const int g = lane >> 2, t = lane & 3;
    const int ti = blockIdx.y * 128, td = blockIdx.x * 128;

    const __half* pb  = g_probs + ((size_t)b * L + ti) * L;
    const __half* vtb = g_vt + ((size_t)b * D + td) * L;

    float acc[4][4][4];
    #pragma unroll
    for (int a = 0; a < 4; a++)
        #pragma unroll
        for (int bb = 0; bb < 4; bb++)
            #pragma unroll
            for (int cc = 0; cc < 4; cc++) acc[a][bb][cc] = 0.0f;

    const int rm = (wid >> 2) * 64, rn = (wid & 3) * 32;

    // 2048 granules of 16B per stage (both tiles), 8 per thread
    #define PV_LOAD(c, st) do { \
        uint32_t sb = smbase + (st) * PV_STAGE; \
        _Pragma("unroll") \
        for (int e = 0; e < 8; ++e) { \
            int idx = e * 256 + tid; \
            int tile = idx >> 10; \
            int rc = idx & 1023; \
            int r = rc >> 3, cg = rc & 7; \
            uint32_t doff = (uint32_t)tile * PV_TILE + (uint32_t)r * PV_RS + cg * 16; \
            size_t goff = (size_t)r * L + (size_t)(c) * 64 + cg * 8; \
            cp16(sb + doff, (tile ? vtb : pb) + goff); \
        } } while (0)

    #define PV_COMPUTE(buf) do { \
        const char* Pt = sm + (buf) * PV_STAGE; \
        const char* Vt = Pt + PV_TILE; \
        _Pragma("unroll") \
        for (int s = 0; s < 4; ++s) { \
            const uint32_t so = (uint32_t)(32 * s + 4 * t); \
            uint32_t a0[4], a1[4], a2[4], a3[4]; \
            _Pragma("unroll") \
            for (int mt = 0; mt < 4; ++mt) { \
                uint32_t r0 = (uint32_t)(rm + mt * 16 + g) * PV_RS + so; \
                a0[mt] = *(const uint32_t*)(Pt + r0); \
                a2[mt] = *(const uint32_t*)(Pt + r0 + 16); \
                a1[mt] = *(const uint32_t*)(Pt + r0 + 8 * PV_RS); \
                a3[mt] = *(const uint32_t*)(Pt + r0 + 8 * PV_RS + 16); \
            } \
            _Pragma("unroll") \
            for (int nt = 0; nt < 4; ++nt) { \
                uint32_t rb = (uint32_t)(rn + nt * 8 + g) * PV_RS + so; \
                uint32_t b0 = *(const uint32_t*)(Vt + rb); \
                uint32_t b1 = *(const uint32_t*)(Vt + rb + 16); \
                _Pragma("unroll") \
                for (int mt = 0; mt < 4; ++mt) \
                    mma_f16(acc[mt][nt], a0[mt], a1[mt], a2[mt], a3[mt], b0, b1); \
            } \
        } } while (0)

    PV_LOAD(0, 0); CP_COMMIT();
    for (int c = 0; c < NC; ++c) {
        CP_WAIT(0);
        __syncthreads();
        if (c + 1 < NC) { PV_LOAD(c + 1, (c + 1) & 1); CP_COMMIT(); }
        PV_COMPUTE(c & 1);
    }

    const int* idxb = g_idx + b * L;
    #pragma unroll
    for (int mt = 0; mt < 4; ++mt) {
        int r0 = rm + mt * 16 + g;
        int i0 = ti + r0, i1 = i0 + 8;
        #pragma unroll
        for (int half = 0; half < 2; ++half) {
            int irow = half ? i1 : i0;
            if (irow < nv) {
                float* orow = out + ((size_t)b * L + idxb[irow]) * D + td;
                #pragma unroll
                for (int nt = 0; nt < 4; ++nt) {
                    int c0 = rn + nt * 8 + 2 * t;
                    *(float2*)(orow + c0) = half
                        ? make_float2(acc[mt][nt][2], acc[mt][nt][3])
                        : make_float2(acc[mt][nt][0], acc[mt][nt][1]);
                }
            }
        }
    }
}

// ---------------------------------------------------------------------------
extern "C" void kernel_launch(void* const* d_in, const int* in_sizes, int n_in,
                              void* d_out, int out_size)
{
    const float* q    = (const float*)d_in[0];
    const float* k    = (const float*)d_in[1];
    const float* v    = (const float*)d_in[2];
    const int*   mask = (const int*)d_in[3];
    float*       out  = (float*)d_out;

    cudaFuncSetAttribute(qk_kernel, cudaFuncAttributeMaxDynamicSharedMemorySize, 2 * QK_STAGE);
    cudaFuncSetAttribute(pv_kernel, cudaFuncAttributeMaxDynamicSharedMemorySize, 2 * PV_STAGE);

    compact_kernel<<<B, 256>>>(mask);
    zerofill_kernel<<<B * L, 256>>>(mask, out);
    prep_qk_kernel<<<dim3((B * L * D / 16) / 256, 2, 1), 256>>>(q, k);
    prep_v_kernel<<<dim3(L / 64, D / 32, B), 256>>>(v);

    dim3 g1(L / 128, L / 128, B);
    qk_kernel<<<g1, 256, 2 * QK_STAGE>>>();

    rowstats_kernel<<<B * L, 256>>>();

    dim3 g3(D / 128, L / 128, B);
    pv_kernel<<<g3, 256, 2 * PV_STAGE>>>(out);
}